// round 1
// baseline (speedup 1.0000x reference)
#include <cuda_runtime.h>
#include <math.h>

// Problem constants
#define BB 2
#define SS 2048
#define DD 1024
#define HH 16
#define HD 64
#define MTOT (BB*SS)   // 4096
#define BHT (BB*HH)    // 32
#define LN_EPS 1e-5f

// Scratch (device globals: allocation-free rule)
__device__ float g_q[(size_t)BHT*SS*HD];      // [BH, S, 64] 16MB
__device__ float g_k[(size_t)BHT*SS*HD];
__device__ float g_v[(size_t)BHT*SS*HD];
__device__ float g_ctx[(size_t)BHT*SS*HD];    // attention output, head-split
__device__ float g_attnout[(size_t)MTOT*DD];  // after Wo proj + bias

// ---------------------------------------------------------------------------
// Kernel 1: QKV projection.  out[m,n] = sum_k X[m,k] * W[n,k] + b[n]
// Both operands K-major (NT GEMM). 64x64 output tile, BK=16, 4x4 per thread.
// Writes head-split layout [BH, S, 64]. Q gets *0.125 scaling.
// grid (M/64=64, H=16, 3), block 256
// ---------------------------------------------------------------------------
__global__ void qkv_gemm(const float* __restrict__ X,
                         const float* __restrict__ Wq, const float* __restrict__ bq,
                         const float* __restrict__ Wk, const float* __restrict__ bk,
                         const float* __restrict__ Wv, const float* __restrict__ bv)
{
    const int which = blockIdx.z;
    const float* W    = (which == 0) ? Wq : (which == 1) ? Wk : Wv;
    const float* bias = (which == 0) ? bq : (which == 1) ? bk : bv;
    float* out        = (which == 0) ? g_q : (which == 1) ? g_k : g_v;
    const float scale = (which == 0) ? 0.125f : 1.0f;   // head_dim^-0.5 = 1/8

    __shared__ float As[64][17];
    __shared__ float Bs[64][17];

    const int m0 = blockIdx.x * 64;
    const int h  = blockIdx.y;
    const int n0 = h * 64;
    const int tid = threadIdx.x;
    const int tx = tid & 15, ty = tid >> 4;

    float acc[4][4] = {};

    for (int k0 = 0; k0 < DD; k0 += 16) {
        #pragma unroll
        for (int r = 0; r < 4; r++) {
            int i = tid + r * 256;
            int row = i >> 4, col = i & 15;
            As[row][col] = X[(size_t)(m0 + row) * DD + k0 + col];
            Bs[row][col] = W[(size_t)(n0 + row) * DD + k0 + col];
        }
        __syncthreads();
        #pragma unroll
        for (int kk = 0; kk < 16; kk++) {
            float a[4], b[4];
            #pragma unroll
            for (int i = 0; i < 4; i++) a[i] = As[ty * 4 + i][kk];
            #pragma unroll
            for (int j = 0; j < 4; j++) b[j] = Bs[tx * 4 + j][kk];
            #pragma unroll
            for (int i = 0; i < 4; i++)
                #pragma unroll
                for (int j = 0; j < 4; j++)
                    acc[i][j] = fmaf(a[i], b[j], acc[i][j]);
        }
        __syncthreads();
    }

    #pragma unroll
    for (int i = 0; i < 4; i++) {
        int m = m0 + ty * 4 + i;
        int b = m >> 11;          // m / S
        int s = m & (SS - 1);     // m % S
        #pragma unroll
        for (int j = 0; j < 4; j++) {
            int d = tx * 4 + j;
            out[((size_t)(b * HH + h) * SS + s) * HD + d] =
                (acc[i][j] + bias[n0 + d]) * scale;
        }
    }
}

// ---------------------------------------------------------------------------
// Kernel 2: flash-style attention with online softmax.
//   per (bh, q-tile of 64): iterate k-tiles of 64:
//     S = Q K^T ; S += extra_attn + mask ; online softmax ; O += P V
// Never materializes the 512MB score tensor (extra_attn read exactly once).
// grid (S/64=32, BH=32), block 256 (16x16, 4x4 per thread), dyn smem 66560B
// ---------------------------------------------------------------------------
__global__ void flash_attn(const float* __restrict__ extra,
                           const float* __restrict__ mask)
{
    extern __shared__ float smem[];
    float (*Qs)[65] = reinterpret_cast<float(*)[65]>(smem);
    float (*Ks)[65] = reinterpret_cast<float(*)[65]>(smem + 64 * 65);
    float (*Vs)[65] = reinterpret_cast<float(*)[65]>(smem + 2 * 64 * 65);
    float (*Ps)[65] = reinterpret_cast<float(*)[65]>(smem + 3 * 64 * 65);

    const int q0 = blockIdx.x * 64;
    const int bh = blockIdx.y;
    const int b  = bh / HH;
    const int tid = threadIdx.x;
    const int tx = tid & 15, ty = tid >> 4;
    const unsigned FULL = 0xffffffffu;

    const float* qptr = g_q + (size_t)bh * SS * HD;
    const float* kptr = g_k + (size_t)bh * SS * HD;
    const float* vptr = g_v + (size_t)bh * SS * HD;

    // Load Q tile once (64x64)
    #pragma unroll
    for (int r = 0; r < 16; r++) {
        int i = tid + r * 256;
        int row = i >> 6, col = i & 63;
        Qs[row][col] = qptr[(size_t)(q0 + row) * HD + col];
    }

    float m_run[4], l_run[4], acc[4][4] = {};
    #pragma unroll
    for (int i = 0; i < 4; i++) { m_run[i] = -INFINITY; l_run[i] = 0.f; }

    for (int k0 = 0; k0 < SS; k0 += 64) {
        __syncthreads();  // protect Ks/Vs/Ps reuse (and Qs on first pass)
        #pragma unroll
        for (int r = 0; r < 16; r++) {
            int i = tid + r * 256;
            int row = i >> 6, col = i & 63;
            Ks[row][col] = kptr[(size_t)(k0 + row) * HD + col];
            Vs[row][col] = vptr[(size_t)(k0 + row) * HD + col];
        }
        __syncthreads();

        // S = Q K^T   (K-dim = 64)
        float s[4][4] = {};
        #pragma unroll
        for (int d = 0; d < 64; d++) {
            float a[4], kk[4];
            #pragma unroll
            for (int i = 0; i < 4; i++) a[i] = Qs[ty * 4 + i][d];
            #pragma unroll
            for (int j = 0; j < 4; j++) kk[j] = Ks[tx * 4 + j][d];
            #pragma unroll
            for (int i = 0; i < 4; i++)
                #pragma unroll
                for (int j = 0; j < 4; j++)
                    s[i][j] = fmaf(a[i], kk[j], s[i][j]);
        }

        // add extra_attn + mask
        #pragma unroll
        for (int i = 0; i < 4; i++) {
            int q = q0 + ty * 4 + i;
            const float* eptr = extra + ((size_t)bh * SS + q) * SS + k0;
            const float* mptr = mask  + ((size_t)b  * SS + q) * SS + k0;
            #pragma unroll
            for (int j = 0; j < 4; j++) {
                int c = tx * 4 + j;
                s[i][j] += eptr[c] + mptr[c];
            }
        }

        // online softmax per row (row spread across 16 tx lanes, width-16 shfl)
        #pragma unroll
        for (int i = 0; i < 4; i++) {
            float mx = fmaxf(fmaxf(s[i][0], s[i][1]), fmaxf(s[i][2], s[i][3]));
            #pragma unroll
            for (int off = 8; off > 0; off >>= 1)
                mx = fmaxf(mx, __shfl_xor_sync(FULL, mx, off, 16));
            float m_new = fmaxf(m_run[i], mx);
            float corr  = __expf(m_run[i] - m_new);
            float ls = 0.f;
            #pragma unroll
            for (int j = 0; j < 4; j++) {
                s[i][j] = __expf(s[i][j] - m_new);
                ls += s[i][j];
            }
            #pragma unroll
            for (int off = 8; off > 0; off >>= 1)
                ls += __shfl_xor_sync(FULL, ls, off, 16);
            l_run[i] = l_run[i] * corr + ls;
            m_run[i] = m_new;
            #pragma unroll
            for (int j = 0; j < 4; j++) {
                acc[i][j] *= corr;
                Ps[ty * 4 + i][tx * 4 + j] = s[i][j];
            }
        }
        __syncthreads();

        // O += P @ V
        #pragma unroll
        for (int jj = 0; jj < 64; jj++) {
            float p[4], v[4];
            #pragma unroll
            for (int i = 0; i < 4; i++) p[i] = Ps[ty * 4 + i][jj];
            #pragma unroll
            for (int j = 0; j < 4; j++) v[j] = Vs[jj][tx * 4 + j];
            #pragma unroll
            for (int i = 0; i < 4; i++)
                #pragma unroll
                for (int j = 0; j < 4; j++)
                    acc[i][j] = fmaf(p[i], v[j], acc[i][j]);
        }
    }

    // write context (normalized)
    #pragma unroll
    for (int i = 0; i < 4; i++) {
        float inv = 1.0f / l_run[i];
        int q = q0 + ty * 4 + i;
        #pragma unroll
        for (int j = 0; j < 4; j++) {
            int d = tx * 4 + j;
            g_ctx[((size_t)bh * SS + q) * HD + d] = acc[i][j] * inv;
        }
    }
}

// ---------------------------------------------------------------------------
// Kernel 3: output projection.  attnout[m,n] = sum_k ctx[m,k] * Wo[n,k] + bo[n]
// ctx gathered from head-split layout. grid (64, 16), block 256
// ---------------------------------------------------------------------------
__global__ void out_proj(const float* __restrict__ Wo, const float* __restrict__ bo)
{
    __shared__ float As[64][17];
    __shared__ float Bs[64][17];

    const int m0 = blockIdx.x * 64;
    const int n0 = blockIdx.y * 64;
    const int tid = threadIdx.x;
    const int tx = tid & 15, ty = tid >> 4;

    float acc[4][4] = {};

    for (int k0 = 0; k0 < DD; k0 += 16) {
        const int h  = k0 >> 6;       // BK=16 never straddles a head (64)
        const int d0 = k0 & 63;
        #pragma unroll
        for (int r = 0; r < 4; r++) {
            int i = tid + r * 256;
            int row = i >> 4, col = i & 15;
            int m = m0 + row;
            int b = m >> 11, s = m & (SS - 1);
            As[row][col] = g_ctx[((size_t)(b * HH + h) * SS + s) * HD + d0 + col];
            Bs[row][col] = Wo[(size_t)(n0 + row) * DD + k0 + col];
        }
        __syncthreads();
        #pragma unroll
        for (int kk = 0; kk < 16; kk++) {
            float a[4], b[4];
            #pragma unroll
            for (int i = 0; i < 4; i++) a[i] = As[ty * 4 + i][kk];
            #pragma unroll
            for (int j = 0; j < 4; j++) b[j] = Bs[tx * 4 + j][kk];
            #pragma unroll
            for (int i = 0; i < 4; i++)
                #pragma unroll
                for (int j = 0; j < 4; j++)
                    acc[i][j] = fmaf(a[i], b[j], acc[i][j]);
        }
        __syncthreads();
    }

    #pragma unroll
    for (int i = 0; i < 4; i++) {
        int m = m0 + ty * 4 + i;
        #pragma unroll
        for (int j = 0; j < 4; j++) {
            int n = n0 + tx * 4 + j;
            g_attnout[(size_t)m * DD + n] = acc[i][j] + bo[n];
        }
    }
}

// ---------------------------------------------------------------------------
// Kernel 4: residual + LayerNorm over D=1024. One block (256 thr) per row.
// ---------------------------------------------------------------------------
__global__ void resid_ln(const float* __restrict__ hid,
                         const float* __restrict__ gamma,
                         const float* __restrict__ beta,
                         float* __restrict__ out)
{
    const int m = blockIdx.x;
    const int tid = threadIdx.x;
    const unsigned FULL = 0xffffffffu;

    float x[4];
    float sum = 0.f, sumsq = 0.f;
    #pragma unroll
    for (int r = 0; r < 4; r++) {
        int i = tid + r * 256;
        x[r] = hid[(size_t)m * DD + i] + g_attnout[(size_t)m * DD + i];
        sum += x[r];
        sumsq += x[r] * x[r];
    }
    #pragma unroll
    for (int off = 16; off > 0; off >>= 1) {
        sum   += __shfl_xor_sync(FULL, sum,   off);
        sumsq += __shfl_xor_sync(FULL, sumsq, off);
    }
    __shared__ float sh[2][8];
    int wid = tid >> 5, lane = tid & 31;
    if (lane == 0) { sh[0][wid] = sum; sh[1][wid] = sumsq; }
    __syncthreads();
    if (tid == 0) {
        float a = 0.f, c = 0.f;
        #pragma unroll
        for (int w = 0; w < 8; w++) { a += sh[0][w]; c += sh[1][w]; }
        sh[0][0] = a; sh[1][0] = c;
    }
    __syncthreads();
    float mu  = sh[0][0] * (1.0f / DD);
    float var = sh[1][0] * (1.0f / DD) - mu * mu;
    float inv = rsqrtf(var + LN_EPS);
    #pragma unroll
    for (int r = 0; r < 4; r++) {
        int i = tid + r * 256;
        out[(size_t)m * DD + i] = (x[r] - mu) * inv * gamma[i] + beta[i];
    }
}

// ---------------------------------------------------------------------------
extern "C" void kernel_launch(void* const* d_in, const int* in_sizes, int n_in,
                              void* d_out, int out_size)
{
    const float* hid   = (const float*)d_in[0];
    const float* mask  = (const float*)d_in[1];
    const float* extra = (const float*)d_in[2];
    const float* Wq = (const float*)d_in[3];  const float* bq = (const float*)d_in[4];
    const float* Wk = (const float*)d_in[5];  const float* bk = (const float*)d_in[6];
    const float* Wv = (const float*)d_in[7];  const float* bv = (const float*)d_in[8];
    const float* Wo = (const float*)d_in[9];  const float* bo = (const float*)d_in[10];
    const float* gamma = (const float*)d_in[11];
    const float* beta  = (const float*)d_in[12];
    float* out = (float*)d_out;

    const int FLASH_SMEM = 4 * 64 * 65 * (int)sizeof(float);  // 66560 B
    cudaFuncSetAttribute(flash_attn, cudaFuncAttributeMaxDynamicSharedMemorySize,
                         FLASH_SMEM);

    qkv_gemm<<<dim3(MTOT / 64, HH, 3), 256>>>(hid, Wq, bq, Wk, bk, Wv, bv);
    flash_attn<<<dim3(SS / 64, BHT), 256, FLASH_SMEM>>>(extra, mask);
    out_proj<<<dim3(MTOT / 64, DD / 64), 256>>>(Wo, bo);
    resid_ln<<<MTOT, 256>>>(hid, gamma, beta, out);
}

// round 3
// speedup vs baseline: 5.1438x; 5.1438x over previous
#include <cuda_runtime.h>
#include <math.h>
#include <stdint.h>

#define BB 2
#define SS 2048
#define DD 1024
#define HH 16
#define HD 64
#define MTOT (BB*SS)   // 4096
#define BHT (BB*HH)    // 32
#define LN_EPS 1e-5f

// Scratch (device globals: allocation-free rule)
__device__ float g_q[(size_t)BHT*SS*HD];      // [BH,S,64]
__device__ float g_k[(size_t)BHT*SS*HD];
__device__ float g_v[(size_t)BHT*SS*HD];
__device__ float g_ctx[(size_t)MTOT*DD];      // [M, D] row-major
__device__ float g_attnout[(size_t)MTOT*DD];

__device__ __forceinline__ uint32_t f2tf(float f) {
    uint32_t u; asm("cvt.rna.tf32.f32 %0, %1;" : "=r"(u) : "f"(f)); return u;
}
__device__ __forceinline__ float f2tff(float f) {
    uint32_t u; asm("cvt.rna.tf32.f32 %0, %1;" : "=r"(u) : "f"(f));
    return __uint_as_float(u);
}
__device__ __forceinline__ void mma8(float c[4], const uint32_t a[4], const uint32_t b[2]) {
    asm volatile("mma.sync.aligned.m16n8k8.row.col.f32.tf32.tf32.f32 "
                 "{%0,%1,%2,%3},{%4,%5,%6,%7},{%8,%9},{%0,%1,%2,%3};"
                 : "+f"(c[0]), "+f"(c[1]), "+f"(c[2]), "+f"(c[3])
                 : "r"(a[0]), "r"(a[1]), "r"(a[2]), "r"(a[3]),
                   "r"(b[0]), "r"(b[1]));
}

// ---------------------------------------------------------------------------
// Tensor-core NT GEMM core: block 128x64, BK=32, 8 warps (4 along M x 2 along N),
// warp tile 32x32 = 2 m16-tiles x 4 n8-tiles. acc[mt][nt][4].
// ---------------------------------------------------------------------------
struct GemmSmem {
    float As[128][36];   // stride 36: float4-aligned, conflict-free frag reads
    float Bs[64][36];
};

__device__ __forceinline__ void gemm_core(const float* __restrict__ A,
                                          const float* __restrict__ W,
                                          int m0, int n0,
                                          GemmSmem* sm, float acc[2][4][4])
{
    const int tid = threadIdx.x;
    const int warp = tid >> 5, lane = tid & 31;
    const int gID = lane >> 2, tig = lane & 3;
    const int wm = warp >> 1, wn = warp & 1;

    for (int k0 = 0; k0 < DD; k0 += 32) {
        #pragma unroll
        for (int r = 0; r < 4; r++) {                // A: 128x32
            int i = tid + r * 256;
            int row = i >> 3, col = (i & 7) * 4;
            float4 x = *(const float4*)&A[(size_t)(m0 + row) * DD + k0 + col];
            sm->As[row][col + 0] = f2tff(x.x);
            sm->As[row][col + 1] = f2tff(x.y);
            sm->As[row][col + 2] = f2tff(x.z);
            sm->As[row][col + 3] = f2tff(x.w);
        }
        #pragma unroll
        for (int r = 0; r < 2; r++) {                // B: 64x32
            int i = tid + r * 256;
            int row = i >> 3, col = (i & 7) * 4;
            float4 x = *(const float4*)&W[(size_t)(n0 + row) * DD + k0 + col];
            sm->Bs[row][col + 0] = f2tff(x.x);
            sm->Bs[row][col + 1] = f2tff(x.y);
            sm->Bs[row][col + 2] = f2tff(x.z);
            sm->Bs[row][col + 3] = f2tff(x.w);
        }
        __syncthreads();
        #pragma unroll
        for (int kc = 0; kc < 32; kc += 8) {
            uint32_t af[2][4], bf[4][2];
            #pragma unroll
            for (int mt = 0; mt < 2; mt++) {
                int base = wm * 32 + mt * 16;
                af[mt][0] = __float_as_uint(sm->As[base + gID    ][kc + tig]);
                af[mt][1] = __float_as_uint(sm->As[base + 8 + gID][kc + tig]);
                af[mt][2] = __float_as_uint(sm->As[base + gID    ][kc + tig + 4]);
                af[mt][3] = __float_as_uint(sm->As[base + 8 + gID][kc + tig + 4]);
            }
            #pragma unroll
            for (int nt = 0; nt < 4; nt++) {
                int nrow = wn * 32 + nt * 8 + gID;
                bf[nt][0] = __float_as_uint(sm->Bs[nrow][kc + tig]);
                bf[nt][1] = __float_as_uint(sm->Bs[nrow][kc + tig + 4]);
            }
            #pragma unroll
            for (int mt = 0; mt < 2; mt++)
                #pragma unroll
                for (int nt = 0; nt < 4; nt++)
                    mma8(acc[mt][nt], af[mt], bf[nt]);
        }
        __syncthreads();
    }
}

// ---------------------------------------------------------------------------
// Kernel 1: QKV projection -> head-split [BH,S,64]. grid (32, 16, 3), block 256
// ---------------------------------------------------------------------------
__global__ __launch_bounds__(256) void qkv_gemm(
    const float* __restrict__ X,
    const float* __restrict__ Wq, const float* __restrict__ bq,
    const float* __restrict__ Wk, const float* __restrict__ bk,
    const float* __restrict__ Wv, const float* __restrict__ bv)
{
    __shared__ GemmSmem sm;
    const int which = blockIdx.z;
    const float* W    = (which == 0) ? Wq : (which == 1) ? Wk : Wv;
    const float* bias = (which == 0) ? bq : (which == 1) ? bk : bv;
    float* out        = (which == 0) ? g_q : (which == 1) ? g_k : g_v;
    const float scale = (which == 0) ? 0.125f : 1.0f;

    const int m0 = blockIdx.x * 128;
    const int head = blockIdx.y;
    const int n0 = head * 64;

    float acc[2][4][4] = {};
    gemm_core(X, W, m0, n0, &sm, acc);

    const int tid = threadIdx.x;
    const int warp = tid >> 5, lane = tid & 31;
    const int gID = lane >> 2, tig = lane & 3;
    const int wm = warp >> 1, wn = warp & 1;

    #pragma unroll
    for (int mt = 0; mt < 2; mt++) {
        #pragma unroll
        for (int nt = 0; nt < 4; nt++) {
            int col = wn * 32 + nt * 8 + 2 * tig;
            #pragma unroll
            for (int half = 0; half < 2; half++) {
                int m = m0 + wm * 32 + mt * 16 + gID + half * 8;
                int b = m >> 11, s = m & (SS - 1);
                size_t base = ((size_t)(b * HH + head) * SS + s) * HD;
                out[base + col    ] = (acc[mt][nt][half*2+0] + bias[n0 + col    ]) * scale;
                out[base + col + 1] = (acc[mt][nt][half*2+1] + bias[n0 + col + 1]) * scale;
            }
        }
    }
}

// ---------------------------------------------------------------------------
// Kernel 2: flash attention with tf32 tensor cores.
// Block: 256 thr (8 warps), q-tile 128 (warp owns 16 rows), k-tile 64.
// grid (S/128=16, BH=32). Writes ctx in [M, D] layout.
// ---------------------------------------------------------------------------
#define FL_SMEM ((128*68 + 64*68 + 128*68 + 64*72) * 4)

__global__ __launch_bounds__(256) void flash_attn(const float* __restrict__ extra,
                                                  const float* __restrict__ mask)
{
    extern __shared__ float smf[];
    float* Qs = smf;                  // [128][68]
    float* Ks = Qs + 128 * 68;        // [64][68]
    float* Ps = Ks + 64 * 68;         // [128][68]
    float* Vs = Ps + 128 * 68;        // [64][72]

    const int q0 = blockIdx.x * 128;
    const int bh = blockIdx.y;
    const int b  = bh >> 4;
    const int h  = bh & 15;
    const int tid = threadIdx.x;
    const int warp = tid >> 5, lane = tid & 31;
    const int gID = lane >> 2, tig = lane & 3;
    const int mrow = warp * 16;
    const unsigned FULL = 0xffffffffu;

    const float* qp = g_q + (size_t)bh * SS * HD;
    const float* kp = g_k + (size_t)bh * SS * HD;
    const float* vp = g_v + (size_t)bh * SS * HD;

    // Q tile 128x64 -> Qs (tf32)
    #pragma unroll
    for (int r = 0; r < 8; r++) {
        int i = tid + r * 256;
        int row = i >> 4, col = (i & 15) * 4;
        float4 x = *(const float4*)&qp[(size_t)(q0 + row) * HD + col];
        Qs[row*68 + col + 0] = f2tff(x.x);
        Qs[row*68 + col + 1] = f2tff(x.y);
        Qs[row*68 + col + 2] = f2tff(x.z);
        Qs[row*68 + col + 3] = f2tff(x.w);
    }

    float m_run[2] = {-INFINITY, -INFINITY};
    float l_run[2] = {0.f, 0.f};
    float o[8][4] = {};

    const int q_r0 = q0 + mrow + gID;

    for (int k0 = 0; k0 < SS; k0 += 64) {
        __syncthreads();
        #pragma unroll
        for (int r = 0; r < 4; r++) {            // K,V tiles 64x64
            int i = tid + r * 256;
            int row = i >> 4, col = (i & 15) * 4;
            float4 xk = *(const float4*)&kp[(size_t)(k0 + row) * HD + col];
            float4 xv = *(const float4*)&vp[(size_t)(k0 + row) * HD + col];
            Ks[row*68 + col + 0] = f2tff(xk.x);
            Ks[row*68 + col + 1] = f2tff(xk.y);
            Ks[row*68 + col + 2] = f2tff(xk.z);
            Ks[row*68 + col + 3] = f2tff(xk.w);
            Vs[row*72 + col + 0] = f2tff(xv.x);
            Vs[row*72 + col + 1] = f2tff(xv.y);
            Vs[row*72 + col + 2] = f2tff(xv.z);
            Vs[row*72 + col + 3] = f2tff(xv.w);
        }
        __syncthreads();

        // S = Q K^T  (warp: 16x64)
        float s[8][4] = {};
        #pragma unroll
        for (int kc = 0; kc < 64; kc += 8) {
            uint32_t af[4];
            af[0] = __float_as_uint(Qs[(mrow + gID    )*68 + kc + tig]);
            af[1] = __float_as_uint(Qs[(mrow + 8 + gID)*68 + kc + tig]);
            af[2] = __float_as_uint(Qs[(mrow + gID    )*68 + kc + tig + 4]);
            af[3] = __float_as_uint(Qs[(mrow + 8 + gID)*68 + kc + tig + 4]);
            #pragma unroll
            for (int nt = 0; nt < 8; nt++) {
                uint32_t bf[2];
                bf[0] = __float_as_uint(Ks[(nt*8 + gID)*68 + kc + tig]);
                bf[1] = __float_as_uint(Ks[(nt*8 + gID)*68 + kc + tig + 4]);
                mma8(s[nt], af, bf);
            }
        }

        // add extra + mask; online softmax (2 rows/thread: gID, gID+8)
        const float* ep0 = extra + ((size_t)bh * SS + q_r0) * SS + k0;
        const float* ep1 = ep0 + (size_t)8 * SS;
        const float* mp0 = mask + ((size_t)b * SS + q_r0) * SS + k0;
        const float* mp1 = mp0 + (size_t)8 * SS;

        float mx0 = -INFINITY, mx1 = -INFINITY;
        #pragma unroll
        for (int nt = 0; nt < 8; nt++) {
            int c = nt * 8 + 2 * tig;
            float2 e0 = *(const float2*)&ep0[c];
            float2 e1 = *(const float2*)&ep1[c];
            float2 k0v = *(const float2*)&mp0[c];
            float2 k1v = *(const float2*)&mp1[c];
            s[nt][0] += e0.x + k0v.x;  s[nt][1] += e0.y + k0v.y;
            s[nt][2] += e1.x + k1v.x;  s[nt][3] += e1.y + k1v.y;
            mx0 = fmaxf(mx0, fmaxf(s[nt][0], s[nt][1]));
            mx1 = fmaxf(mx1, fmaxf(s[nt][2], s[nt][3]));
        }
        mx0 = fmaxf(mx0, __shfl_xor_sync(FULL, mx0, 1));
        mx0 = fmaxf(mx0, __shfl_xor_sync(FULL, mx0, 2));
        mx1 = fmaxf(mx1, __shfl_xor_sync(FULL, mx1, 1));
        mx1 = fmaxf(mx1, __shfl_xor_sync(FULL, mx1, 2));

        float mn0 = fmaxf(m_run[0], mx0);
        float mn1 = fmaxf(m_run[1], mx1);
        float corr0 = __expf(m_run[0] - mn0);
        float corr1 = __expf(m_run[1] - mn1);
        float ls0 = 0.f, ls1 = 0.f;
        #pragma unroll
        for (int nt = 0; nt < 8; nt++) {
            s[nt][0] = __expf(s[nt][0] - mn0);
            s[nt][1] = __expf(s[nt][1] - mn0);
            s[nt][2] = __expf(s[nt][2] - mn1);
            s[nt][3] = __expf(s[nt][3] - mn1);
            ls0 += s[nt][0] + s[nt][1];
            ls1 += s[nt][2] + s[nt][3];
        }
        ls0 += __shfl_xor_sync(FULL, ls0, 1);
        ls0 += __shfl_xor_sync(FULL, ls0, 2);
        ls1 += __shfl_xor_sync(FULL, ls1, 1);
        ls1 += __shfl_xor_sync(FULL, ls1, 2);
        l_run[0] = l_run[0] * corr0 + ls0;
        l_run[1] = l_run[1] * corr1 + ls1;
        m_run[0] = mn0;  m_run[1] = mn1;

        #pragma unroll
        for (int nt = 0; nt < 8; nt++) {
            o[nt][0] *= corr0;  o[nt][1] *= corr0;
            o[nt][2] *= corr1;  o[nt][3] *= corr1;
            int c = nt * 8 + 2 * tig;
            Ps[(mrow + gID    )*68 + c    ] = f2tff(s[nt][0]);
            Ps[(mrow + gID    )*68 + c + 1] = f2tff(s[nt][1]);
            Ps[(mrow + 8 + gID)*68 + c    ] = f2tff(s[nt][2]);
            Ps[(mrow + 8 + gID)*68 + c + 1] = f2tff(s[nt][3]);
        }
        __syncwarp();

        // O += P @ V  (warp: 16x64)
        #pragma unroll
        for (int kc = 0; kc < 64; kc += 8) {
            uint32_t af[4];
            af[0] = __float_as_uint(Ps[(mrow + gID    )*68 + kc + tig]);
            af[1] = __float_as_uint(Ps[(mrow + 8 + gID)*68 + kc + tig]);
            af[2] = __float_as_uint(Ps[(mrow + gID    )*68 + kc + tig + 4]);
            af[3] = __float_as_uint(Ps[(mrow + 8 + gID)*68 + kc + tig + 4]);
            #pragma unroll
            for (int nt = 0; nt < 8; nt++) {
                uint32_t bf[2];
                bf[0] = __float_as_uint(Vs[(kc + tig    )*72 + nt*8 + gID]);
                bf[1] = __float_as_uint(Vs[(kc + tig + 4)*72 + nt*8 + gID]);
                mma8(o[nt], af, bf);
            }
        }
    }

    // write ctx [M, D]
    float inv0 = 1.0f / l_run[0];
    float inv1 = 1.0f / l_run[1];
    #pragma unroll
    for (int nt = 0; nt < 8; nt++) {
        int c = nt * 8 + 2 * tig;
        size_t base0 = ((size_t)(b * SS + q_r0    )) * DD + h * 64 + c;
        size_t base1 = ((size_t)(b * SS + q_r0 + 8)) * DD + h * 64 + c;
        g_ctx[base0    ] = o[nt][0] * inv0;
        g_ctx[base0 + 1] = o[nt][1] * inv0;
        g_ctx[base1    ] = o[nt][2] * inv1;
        g_ctx[base1 + 1] = o[nt][3] * inv1;
    }
}

// ---------------------------------------------------------------------------
// Kernel 3: output projection (tensor core). grid (32, 16), block 256
// ---------------------------------------------------------------------------
__global__ __launch_bounds__(256) void out_proj(const float* __restrict__ Wo,
                                                const float* __restrict__ bo)
{
    __shared__ GemmSmem sm;
    const int m0 = blockIdx.x * 128;
    const int n0 = blockIdx.y * 64;

    float acc[2][4][4] = {};
    gemm_core(g_ctx, Wo, m0, n0, &sm, acc);

    const int tid = threadIdx.x;
    const int warp = tid >> 5, lane = tid & 31;
    const int gID = lane >> 2, tig = lane & 3;
    const int wm = warp >> 1, wn = warp & 1;

    #pragma unroll
    for (int mt = 0; mt < 2; mt++) {
        #pragma unroll
        for (int nt = 0; nt < 4; nt++) {
            int col = n0 + wn * 32 + nt * 8 + 2 * tig;
            #pragma unroll
            for (int half = 0; half < 2; half++) {
                int m = m0 + wm * 32 + mt * 16 + gID + half * 8;
                g_attnout[(size_t)m * DD + col    ] = acc[mt][nt][half*2+0] + bo[col    ];
                g_attnout[(size_t)m * DD + col + 1] = acc[mt][nt][half*2+1] + bo[col + 1];
            }
        }
    }
}

// ---------------------------------------------------------------------------
// Kernel 4: residual + LayerNorm (unchanged)
// ---------------------------------------------------------------------------
__global__ void resid_ln(const float* __restrict__ hid,
                         const float* __restrict__ gamma,
                         const float* __restrict__ beta,
                         float* __restrict__ out)
{
    const int m = blockIdx.x;
    const int tid = threadIdx.x;
    const unsigned FULL = 0xffffffffu;

    float x[4];
    float sum = 0.f, sumsq = 0.f;
    #pragma unroll
    for (int r = 0; r < 4; r++) {
        int i = tid + r * 256;
        x[r] = hid[(size_t)m * DD + i] + g_attnout[(size_t)m * DD + i];
        sum += x[r];
        sumsq += x[r] * x[r];
    }
    #pragma unroll
    for (int off = 16; off > 0; off >>= 1) {
        sum   += __shfl_xor_sync(FULL, sum,   off);
        sumsq += __shfl_xor_sync(FULL, sumsq, off);
    }
    __shared__ float sh[2][8];
    int wid = tid >> 5, lane = tid & 31;
    if (lane == 0) { sh[0][wid] = sum; sh[1][wid] = sumsq; }
    __syncthreads();
    if (tid == 0) {
        float a = 0.f, c = 0.f;
        #pragma unroll
        for (int w = 0; w < 8; w++) { a += sh[0][w]; c += sh[1][w]; }
        sh[0][0] = a; sh[1][0] = c;
    }
    __syncthreads();
    float mu  = sh[0][0] * (1.0f / DD);
    float var = sh[1][0] * (1.0f / DD) - mu * mu;
    float inv = rsqrtf(var + LN_EPS);
    #pragma unroll
    for (int r = 0; r < 4; r++) {
        int i = tid + r * 256;
        out[(size_t)m * DD + i] = (x[r] - mu) * inv * gamma[i] + beta[i];
    }
}

// ---------------------------------------------------------------------------
extern "C" void kernel_launch(void* const* d_in, const int* in_sizes, int n_in,
                              void* d_out, int out_size)
{
    const float* hid   = (const float*)d_in[0];
    const float* mask  = (const float*)d_in[1];
    const float* extra = (const float*)d_in[2];
    const float* Wq = (const float*)d_in[3];  const float* bq = (const float*)d_in[4];
    const float* Wk = (const float*)d_in[5];  const float* bk = (const float*)d_in[6];
    const float* Wv = (const float*)d_in[7];  const float* bv = (const float*)d_in[8];
    const float* Wo = (const float*)d_in[9];  const float* bo = (const float*)d_in[10];
    const float* gamma = (const float*)d_in[11];
    const float* beta  = (const float*)d_in[12];
    float* out = (float*)d_out;

    cudaFuncSetAttribute(flash_attn, cudaFuncAttributeMaxDynamicSharedMemorySize,
                         FL_SMEM);

    qkv_gemm<<<dim3(MTOT / 128, HH, 3), 256>>>(hid, Wq, bq, Wk, bk, Wv, bv);
    flash_attn<<<dim3(SS / 128, BHT), 256, FL_SMEM>>>(extra, mask);
    out_proj<<<dim3(MTOT / 128, DD / 64), 256>>>(Wo, bo);
    resid_ln<<<MTOT, 256>>>(hid, gamma, beta, out);
}

// round 4
// speedup vs baseline: 6.8961x; 1.3407x over previous
#include <cuda_runtime.h>
#include <cuda_bf16.h>
#include <math.h>
#include <stdint.h>

#define BB 2
#define SS 2048
#define DD 1024
#define HH 16
#define HD 64
#define MTOT (BB*SS)   // 4096
#define BHT (BB*HH)    // 32
#define LN_EPS 1e-5f

typedef __nv_bfloat16 bf16;
typedef __nv_bfloat162 bf162;

// ---------------- global bf16 scratch (allocation-free rule) ---------------
__device__ bf16 g_xb [(size_t)MTOT*DD];
__device__ bf16 g_wqb[(size_t)DD*DD];
__device__ bf16 g_wkb[(size_t)DD*DD];
__device__ bf16 g_wvb[(size_t)DD*DD];
__device__ bf16 g_wob[(size_t)DD*DD];
__device__ bf16 g_q  [(size_t)BHT*SS*HD];   // [bh][s][d]
__device__ bf16 g_k  [(size_t)BHT*SS*HD];   // [bh][s][d]
__device__ bf16 g_vt [(size_t)BHT*HD*SS];   // [bh][d][s]  (transposed!)
__device__ bf16 g_ctx[(size_t)MTOT*DD];     // [m][D]
__device__ float g_attnout[(size_t)MTOT*DD];

__device__ __forceinline__ uint32_t packbf(float lo, float hi) {
    bf162 h;
    h.x = __float2bfloat16_rn(lo);
    h.y = __float2bfloat16_rn(hi);
    return *(uint32_t*)&h;
}

__device__ __forceinline__ void mma16(float c[4], const uint32_t a[4], const uint32_t b[2]) {
    asm volatile("mma.sync.aligned.m16n8k16.row.col.f32.bf16.bf16.f32 "
                 "{%0,%1,%2,%3},{%4,%5,%6,%7},{%8,%9},{%0,%1,%2,%3};"
                 : "+f"(c[0]), "+f"(c[1]), "+f"(c[2]), "+f"(c[3])
                 : "r"(a[0]), "r"(a[1]), "r"(a[2]), "r"(a[3]),
                   "r"(b[0]), "r"(b[1]));
}

// ---------------------------------------------------------------------------
// Kernel 0: fp32 -> bf16 convert (grid-stride over float4 groups)
// ---------------------------------------------------------------------------
__global__ void to_bf16(const float* __restrict__ src, bf16* __restrict__ dst, int n4)
{
    int i = blockIdx.x * blockDim.x + threadIdx.x;
    int stride = gridDim.x * blockDim.x;
    for (; i < n4; i += stride) {
        float4 x = ((const float4*)src)[i];
        uint2 o;
        o.x = packbf(x.x, x.y);
        o.y = packbf(x.z, x.w);
        ((uint2*)dst)[i] = o;
    }
}

// ---------------------------------------------------------------------------
// Shared NT GEMM core: C[128m][128n] += A[128][1024] * B[128][1024]^T
// (both operands k-major, lda=ldb=1024=DD, K=DD). 8 warps = 2(M) x 4(N),
// warp tile 64x32 (4 m16 x 4 n8), BK=32.
// ---------------------------------------------------------------------------
__device__ __forceinline__ void gemm_core_bf16(
    const bf16* __restrict__ A, const bf16* __restrict__ B,
    bf16* As, bf16* Bs, float acc[4][4][4])
{
    const int tid = threadIdx.x;
    const int warp = tid >> 5, lane = tid & 31;
    const int gID = lane >> 2, tig = lane & 3;
    const int wm = warp >> 2, wn = warp & 3;

    for (int k0 = 0; k0 < DD; k0 += 32) {
        #pragma unroll
        for (int r = 0; r < 2; r++) {
            int c = tid + r * 256;
            int row = c >> 2, col = (c & 3) * 8;
            *(uint4*)&As[row*40 + col] = *(const uint4*)&A[(size_t)row*DD + k0 + col];
            *(uint4*)&Bs[row*40 + col] = *(const uint4*)&B[(size_t)row*DD + k0 + col];
        }
        __syncthreads();
        #pragma unroll
        for (int kc = 0; kc < 32; kc += 16) {
            uint32_t a[4][4], b[4][2];
            #pragma unroll
            for (int mt = 0; mt < 4; mt++) {
                int base = wm * 64 + mt * 16;
                a[mt][0] = *(uint32_t*)&As[(base + gID    )*40 + kc +     2*tig];
                a[mt][1] = *(uint32_t*)&As[(base + 8 + gID)*40 + kc +     2*tig];
                a[mt][2] = *(uint32_t*)&As[(base + gID    )*40 + kc + 8 + 2*tig];
                a[mt][3] = *(uint32_t*)&As[(base + 8 + gID)*40 + kc + 8 + 2*tig];
            }
            #pragma unroll
            for (int nt = 0; nt < 4; nt++) {
                int row = wn * 32 + nt * 8 + gID;
                b[nt][0] = *(uint32_t*)&Bs[row*40 + kc +     2*tig];
                b[nt][1] = *(uint32_t*)&Bs[row*40 + kc + 8 + 2*tig];
            }
            #pragma unroll
            for (int mt = 0; mt < 4; mt++)
                #pragma unroll
                for (int nt = 0; nt < 4; nt++)
                    mma16(acc[mt][nt], a[mt], b[nt]);
        }
        __syncthreads();
    }
}

// ---------------------------------------------------------------------------
// Kernel 1: Q,K projection -> head-split bf16 [bh][s][64]. grid (32,8,2)
// ---------------------------------------------------------------------------
__global__ __launch_bounds__(256) void qk_gemm(const float* __restrict__ bq,
                                               const float* __restrict__ bk)
{
    __shared__ bf16 As[128*40], Bs[128*40];
    const int which = blockIdx.z;
    const bf16* W     = which ? g_wkb : g_wqb;
    const float* bias = which ? bk : bq;
    bf16* out         = which ? g_k : g_q;
    const float scale = which ? 1.0f : 0.125f;

    const int m0 = blockIdx.x * 128;
    const int n0 = blockIdx.y * 128;

    float acc[4][4][4] = {};
    gemm_core_bf16(g_xb + (size_t)m0 * DD, W + (size_t)n0 * DD, As, Bs, acc);

    const int tid = threadIdx.x;
    const int warp = tid >> 5, lane = tid & 31;
    const int gID = lane >> 2, tig = lane & 3;
    const int wm = warp >> 2, wn = warp & 3;

    #pragma unroll
    for (int mt = 0; mt < 4; mt++) {
        #pragma unroll
        for (int nt = 0; nt < 4; nt++) {
            int n = n0 + wn * 32 + nt * 8 + 2 * tig;
            int head = n >> 6, d = n & 63;
            float b0 = bias[n], b1 = bias[n + 1];
            #pragma unroll
            for (int half = 0; half < 2; half++) {
                int m = m0 + wm * 64 + mt * 16 + gID + half * 8;
                int bb = m >> 11, s = m & (SS - 1);
                uint32_t p = packbf((acc[mt][nt][half*2+0] + b0) * scale,
                                    (acc[mt][nt][half*2+1] + b1) * scale);
                *(uint32_t*)&out[((size_t)(bb * HH + head) * SS + s) * HD + d] = p;
            }
        }
    }
}

// ---------------------------------------------------------------------------
// Kernel 2: V projection TRANSPOSED: C[d][s] = Wv[d,:] . X_b[s,:]
// grid (8, 16, B). Writes g_vt [bh][d][s] bf16.
// ---------------------------------------------------------------------------
__global__ __launch_bounds__(256) void v_gemm(const float* __restrict__ bv)
{
    __shared__ bf16 As[128*40], Bs[128*40];
    const int m0 = blockIdx.x * 128;          // d
    const int n0 = blockIdx.y * 128;          // s
    const int bb = blockIdx.z;

    float acc[4][4][4] = {};
    gemm_core_bf16(g_wvb + (size_t)m0 * DD,
                   g_xb + ((size_t)bb * SS + n0) * DD, As, Bs, acc);

    const int tid = threadIdx.x;
    const int warp = tid >> 5, lane = tid & 31;
    const int gID = lane >> 2, tig = lane & 3;
    const int wm = warp >> 2, wn = warp & 3;

    #pragma unroll
    for (int mt = 0; mt < 4; mt++) {
        #pragma unroll
        for (int nt = 0; nt < 4; nt++) {
            int s = n0 + wn * 32 + nt * 8 + 2 * tig;
            #pragma unroll
            for (int half = 0; half < 2; half++) {
                int d = m0 + wm * 64 + mt * 16 + gID + half * 8;
                int head = d >> 6;
                float bia = bv[d];
                uint32_t p = packbf(acc[mt][nt][half*2+0] + bia,
                                    acc[mt][nt][half*2+1] + bia);
                *(uint32_t*)&g_vt[((size_t)(bb * HH + head) * HD + (d & 63)) * SS + s] = p;
            }
        }
    }
}

// ---------------------------------------------------------------------------
// Kernel 3: flash attention, bf16 MMA, P kept in registers.
// Block 256 thr (8 warps), q-tile 128 (warp owns 16 rows), k-tile 64.
// grid (S/128=16, BH=32). ctx written bf16 [m][D].
// ---------------------------------------------------------------------------
__global__ __launch_bounds__(256) void flash_attn(const float* __restrict__ extra,
                                                  const float* __restrict__ mask)
{
    __shared__ bf16 Qs[128*72];
    __shared__ bf16 Ks[64*72];
    __shared__ bf16 Vts[64*72];   // [d][kv]

    const int q0 = blockIdx.x * 128;
    const int bh = blockIdx.y;
    const int b  = bh >> 4;
    const int h  = bh & 15;
    const int tid = threadIdx.x;
    const int warp = tid >> 5, lane = tid & 31;
    const int gID = lane >> 2, tig = lane & 3;
    const int mrow = warp * 16;
    const unsigned FULL = 0xffffffffu;

    const bf16* qp  = g_q  + (size_t)bh * SS * HD;
    const bf16* kp  = g_k  + (size_t)bh * SS * HD;
    const bf16* vtp = g_vt + (size_t)bh * HD * SS;

    // Q tile 128x64
    #pragma unroll
    for (int r = 0; r < 4; r++) {
        int c = tid + r * 256;
        int row = c >> 3, seg = (c & 7) * 8;
        *(uint4*)&Qs[row*72 + seg] = *(const uint4*)&qp[(size_t)(q0 + row) * HD + seg];
    }

    float m_run[2] = {-INFINITY, -INFINITY};
    float l_run[2] = {0.f, 0.f};
    float o[8][4] = {};
    const int q_r0 = q0 + mrow + gID;

    for (int k0 = 0; k0 < SS; k0 += 64) {
        __syncthreads();
        #pragma unroll
        for (int r = 0; r < 2; r++) {
            int c = tid + r * 256;
            int row = c >> 3, seg = (c & 7) * 8;
            *(uint4*)&Ks [row*72 + seg] = *(const uint4*)&kp [(size_t)(k0 + row) * HD + seg];
            *(uint4*)&Vts[row*72 + seg] = *(const uint4*)&vtp[(size_t)row * SS + k0 + seg];
        }
        __syncthreads();

        // S = Q K^T   (warp 16 x 64, contraction d=64)
        float s[8][4] = {};
        #pragma unroll
        for (int kc = 0; kc < 64; kc += 16) {
            uint32_t a[4];
            a[0] = *(uint32_t*)&Qs[(mrow + gID    )*72 + kc +     2*tig];
            a[1] = *(uint32_t*)&Qs[(mrow + 8 + gID)*72 + kc +     2*tig];
            a[2] = *(uint32_t*)&Qs[(mrow + gID    )*72 + kc + 8 + 2*tig];
            a[3] = *(uint32_t*)&Qs[(mrow + 8 + gID)*72 + kc + 8 + 2*tig];
            #pragma unroll
            for (int nt = 0; nt < 8; nt++) {
                uint32_t bfr[2];
                bfr[0] = *(uint32_t*)&Ks[(nt*8 + gID)*72 + kc +     2*tig];
                bfr[1] = *(uint32_t*)&Ks[(nt*8 + gID)*72 + kc + 8 + 2*tig];
                mma16(s[nt], a, bfr);
            }
        }

        // add extra + mask
        const float* ep0 = extra + ((size_t)bh * SS + q_r0) * SS + k0;
        const float* ep1 = ep0 + (size_t)8 * SS;
        const float* mp0 = mask + ((size_t)b * SS + q_r0) * SS + k0;
        const float* mp1 = mp0 + (size_t)8 * SS;

        float mx0 = -INFINITY, mx1 = -INFINITY;
        #pragma unroll
        for (int nt = 0; nt < 8; nt++) {
            int c = nt * 8 + 2 * tig;
            float2 e0 = *(const float2*)&ep0[c];
            float2 e1 = *(const float2*)&ep1[c];
            float2 m0v = *(const float2*)&mp0[c];
            float2 m1v = *(const float2*)&mp1[c];
            s[nt][0] += e0.x + m0v.x;  s[nt][1] += e0.y + m0v.y;
            s[nt][2] += e1.x + m1v.x;  s[nt][3] += e1.y + m1v.y;
            mx0 = fmaxf(mx0, fmaxf(s[nt][0], s[nt][1]));
            mx1 = fmaxf(mx1, fmaxf(s[nt][2], s[nt][3]));
        }
        mx0 = fmaxf(mx0, __shfl_xor_sync(FULL, mx0, 1));
        mx0 = fmaxf(mx0, __shfl_xor_sync(FULL, mx0, 2));
        mx1 = fmaxf(mx1, __shfl_xor_sync(FULL, mx1, 1));
        mx1 = fmaxf(mx1, __shfl_xor_sync(FULL, mx1, 2));

        float mn0 = fmaxf(m_run[0], mx0);
        float mn1 = fmaxf(m_run[1], mx1);
        float corr0 = __expf(m_run[0] - mn0);
        float corr1 = __expf(m_run[1] - mn1);
        float ls0 = 0.f, ls1 = 0.f;
        #pragma unroll
        for (int nt = 0; nt < 8; nt++) {
            s[nt][0] = __expf(s[nt][0] - mn0);
            s[nt][1] = __expf(s[nt][1] - mn0);
            s[nt][2] = __expf(s[nt][2] - mn1);
            s[nt][3] = __expf(s[nt][3] - mn1);
            ls0 += s[nt][0] + s[nt][1];
            ls1 += s[nt][2] + s[nt][3];
        }
        ls0 += __shfl_xor_sync(FULL, ls0, 1);
        ls0 += __shfl_xor_sync(FULL, ls0, 2);
        ls1 += __shfl_xor_sync(FULL, ls1, 1);
        ls1 += __shfl_xor_sync(FULL, ls1, 2);
        l_run[0] = l_run[0] * corr0 + ls0;
        l_run[1] = l_run[1] * corr1 + ls1;
        m_run[0] = mn0;  m_run[1] = mn1;

        #pragma unroll
        for (int nt = 0; nt < 8; nt++) {
            o[nt][0] *= corr0;  o[nt][1] *= corr0;
            o[nt][2] *= corr1;  o[nt][3] *= corr1;
        }

        // O += P @ V ; P packed straight from the score fragments
        #pragma unroll
        for (int t = 0; t < 4; t++) {
            int kc = t * 16;
            uint32_t a[4];
            a[0] = packbf(s[2*t    ][0], s[2*t    ][1]);
            a[1] = packbf(s[2*t    ][2], s[2*t    ][3]);
            a[2] = packbf(s[2*t + 1][0], s[2*t + 1][1]);
            a[3] = packbf(s[2*t + 1][2], s[2*t + 1][3]);
            #pragma unroll
            for (int nt = 0; nt < 8; nt++) {
                uint32_t bfr[2];
                bfr[0] = *(uint32_t*)&Vts[(nt*8 + gID)*72 + kc +     2*tig];
                bfr[1] = *(uint32_t*)&Vts[(nt*8 + gID)*72 + kc + 8 + 2*tig];
                mma16(o[nt], a, bfr);
            }
        }
    }

    // write ctx bf16 [m][D]
    float inv0 = 1.0f / l_run[0];
    float inv1 = 1.0f / l_run[1];
    #pragma unroll
    for (int nt = 0; nt < 8; nt++) {
        int c = nt * 8 + 2 * tig;
        size_t base0 = ((size_t)(b * SS + q_r0    )) * DD + h * 64 + c;
        size_t base1 = ((size_t)(b * SS + q_r0 + 8)) * DD + h * 64 + c;
        *(uint32_t*)&g_ctx[base0] = packbf(o[nt][0] * inv0, o[nt][1] * inv0);
        *(uint32_t*)&g_ctx[base1] = packbf(o[nt][2] * inv1, o[nt][3] * inv1);
    }
}

// ---------------------------------------------------------------------------
// Kernel 4: output projection. grid (32, 8). fp32 out for residual precision.
// ---------------------------------------------------------------------------
__global__ __launch_bounds__(256) void out_proj(const float* __restrict__ bo)
{
    __shared__ bf16 As[128*40], Bs[128*40];
    const int m0 = blockIdx.x * 128;
    const int n0 = blockIdx.y * 128;

    float acc[4][4][4] = {};
    gemm_core_bf16(g_ctx + (size_t)m0 * DD, g_wob + (size_t)n0 * DD, As, Bs, acc);

    const int tid = threadIdx.x;
    const int warp = tid >> 5, lane = tid & 31;
    const int gID = lane >> 2, tig = lane & 3;
    const int wm = warp >> 2, wn = warp & 3;

    #pragma unroll
    for (int mt = 0; mt < 4; mt++) {
        #pragma unroll
        for (int nt = 0; nt < 4; nt++) {
            int n = n0 + wn * 32 + nt * 8 + 2 * tig;
            float b0 = bo[n], b1 = bo[n + 1];
            #pragma unroll
            for (int half = 0; half < 2; half++) {
                int m = m0 + wm * 64 + mt * 16 + gID + half * 8;
                float2 v;
                v.x = acc[mt][nt][half*2+0] + b0;
                v.y = acc[mt][nt][half*2+1] + b1;
                *(float2*)&g_attnout[(size_t)m * DD + n] = v;
            }
        }
    }
}

// ---------------------------------------------------------------------------
// Kernel 5: residual + LayerNorm
// ---------------------------------------------------------------------------
__global__ void resid_ln(const float* __restrict__ hid,
                         const float* __restrict__ gamma,
                         const float* __restrict__ beta,
                         float* __restrict__ out)
{
    const int m = blockIdx.x;
    const int tid = threadIdx.x;
    const unsigned FULL = 0xffffffffu;

    float x[4];
    float sum = 0.f, sumsq = 0.f;
    #pragma unroll
    for (int r = 0; r < 4; r++) {
        int i = tid + r * 256;
        x[r] = hid[(size_t)m * DD + i] + g_attnout[(size_t)m * DD + i];
        sum += x[r];
        sumsq += x[r] * x[r];
    }
    #pragma unroll
    for (int off = 16; off > 0; off >>= 1) {
        sum   += __shfl_xor_sync(FULL, sum,   off);
        sumsq += __shfl_xor_sync(FULL, sumsq, off);
    }
    __shared__ float sh[2][8];
    int wid = tid >> 5, lane = tid & 31;
    if (lane == 0) { sh[0][wid] = sum; sh[1][wid] = sumsq; }
    __syncthreads();
    if (tid == 0) {
        float a = 0.f, c = 0.f;
        #pragma unroll
        for (int w = 0; w < 8; w++) { a += sh[0][w]; c += sh[1][w]; }
        sh[0][0] = a; sh[1][0] = c;
    }
    __syncthreads();
    float mu  = sh[0][0] * (1.0f / DD);
    float var = sh[1][0] * (1.0f / DD) - mu * mu;
    float inv = rsqrtf(var + LN_EPS);
    #pragma unroll
    for (int r = 0; r < 4; r++) {
        int i = tid + r * 256;
        out[(size_t)m * DD + i] = (x[r] - mu) * inv * gamma[i] + beta[i];
    }
}

// ---------------------------------------------------------------------------
extern "C" void kernel_launch(void* const* d_in, const int* in_sizes, int n_in,
                              void* d_out, int out_size)
{
    const float* hid   = (const float*)d_in[0];
    const float* mask  = (const float*)d_in[1];
    const float* extra = (const float*)d_in[2];
    const float* Wq = (const float*)d_in[3];  const float* bq = (const float*)d_in[4];
    const float* Wk = (const float*)d_in[5];  const float* bk = (const float*)d_in[6];
    const float* Wv = (const float*)d_in[7];  const float* bv = (const float*)d_in[8];
    const float* Wo = (const float*)d_in[9];  const float* bo = (const float*)d_in[10];
    const float* gamma = (const float*)d_in[11];
    const float* beta  = (const float*)d_in[12];
    float* out = (float*)d_out;

    bf16 *d_xb, *d_wqb, *d_wkb, *d_wvb, *d_wob;
    cudaGetSymbolAddress((void**)&d_xb,  g_xb);
    cudaGetSymbolAddress((void**)&d_wqb, g_wqb);
    cudaGetSymbolAddress((void**)&d_wkb, g_wkb);
    cudaGetSymbolAddress((void**)&d_wvb, g_wvb);
    cudaGetSymbolAddress((void**)&d_wob, g_wob);

    to_bf16<<<2048, 256>>>(hid, d_xb,  MTOT*DD/4);
    to_bf16<<<1024, 256>>>(Wq,  d_wqb, DD*DD/4);
    to_bf16<<<1024, 256>>>(Wk,  d_wkb, DD*DD/4);
    to_bf16<<<1024, 256>>>(Wv,  d_wvb, DD*DD/4);
    to_bf16<<<1024, 256>>>(Wo,  d_wob, DD*DD/4);

    qk_gemm<<<dim3(MTOT/128, DD/128, 2), 256>>>(bq, bk);
    v_gemm <<<dim3(DD/128, SS/128, BB), 256>>>(bv);
    flash_attn<<<dim3(SS/128, BHT), 256>>>(extra, mask);
    out_proj<<<dim3(MTOT/128, DD/128), 256>>>(bo);
    resid_ln<<<MTOT, 256>>>(hid, gamma, beta, out);
}

// round 6
// speedup vs baseline: 8.5767x; 1.2437x over previous
#include <cuda_runtime.h>
#include <cuda_bf16.h>
#include <math.h>
#include <stdint.h>

#define BB 2
#define SS 2048
#define DD 1024
#define HH 16
#define HD 64
#define MTOT (BB*SS)   // 4096
#define BHT (BB*HH)    // 32
#define LN_EPS 1e-5f

typedef __nv_bfloat16 bf16;
typedef __nv_bfloat162 bf162;

// ---------------- global bf16 scratch (allocation-free rule) ---------------
__device__ bf16 g_xb [(size_t)MTOT*DD];
__device__ bf16 g_wqb[(size_t)DD*DD];
__device__ bf16 g_wkb[(size_t)DD*DD];
__device__ bf16 g_wvb[(size_t)DD*DD];
__device__ bf16 g_wob[(size_t)DD*DD];
__device__ bf16 g_q  [(size_t)BHT*SS*HD];   // [bh][s][d]
__device__ bf16 g_k  [(size_t)BHT*SS*HD];   // [bh][s][d]
__device__ bf16 g_vt [(size_t)BHT*HD*SS];   // [bh][d][s]  transposed
__device__ bf16 g_ctx[(size_t)MTOT*DD];     // [m][D]
__device__ float g_attnout[(size_t)MTOT*DD];

#define CP16(dst, src) asm volatile("cp.async.ca.shared.global [%0], [%1], 16;" :: "r"(dst), "l"(src))
#define CPCOMMIT()     asm volatile("cp.async.commit_group;")
#define CPWAIT(N)      asm volatile("cp.async.wait_group %0;" :: "n"(N))

__device__ __forceinline__ uint32_t packbf(float lo, float hi) {
    bf162 h;
    h.x = __float2bfloat16_rn(lo);
    h.y = __float2bfloat16_rn(hi);
    return *(uint32_t*)&h;
}
__device__ __forceinline__ void mma16(float c[4], const uint32_t a[4], const uint32_t b[2]) {
    asm volatile("mma.sync.aligned.m16n8k16.row.col.f32.bf16.bf16.f32 "
                 "{%0,%1,%2,%3},{%4,%5,%6,%7},{%8,%9},{%0,%1,%2,%3};"
                 : "+f"(c[0]), "+f"(c[1]), "+f"(c[2]), "+f"(c[3])
                 : "r"(a[0]), "r"(a[1]), "r"(a[2]), "r"(a[3]),
                   "r"(b[0]), "r"(b[1]));
}

// ---------------------------------------------------------------------------
// Converts
// ---------------------------------------------------------------------------
__global__ void conv_x(const float* __restrict__ src, bf16* __restrict__ dst, int n4)
{
    int i = blockIdx.x * blockDim.x + threadIdx.x;
    int stride = gridDim.x * blockDim.x;
    for (; i < n4; i += stride) {
        float4 x = ((const float4*)src)[i];
        uint2 o;
        o.x = packbf(x.x, x.y);
        o.y = packbf(x.z, x.w);
        ((uint2*)dst)[i] = o;
    }
}
__global__ void conv_w2(const float* __restrict__ s0, const float* __restrict__ s1,
                        bf16* __restrict__ d0, bf16* __restrict__ d1)
{
    const int n4 = DD * DD / 4;
    int i = blockIdx.x * blockDim.x + threadIdx.x;
    int stride = gridDim.x * blockDim.x;
    for (; i < 2 * n4; i += stride) {
        const float4 x = (i < n4) ? ((const float4*)s0)[i] : ((const float4*)s1)[i - n4];
        uint2 o;
        o.x = packbf(x.x, x.y);
        o.y = packbf(x.z, x.w);
        if (i < n4) ((uint2*)d0)[i] = o; else ((uint2*)d1)[i - n4] = o;
    }
}

// ---------------------------------------------------------------------------
// cp.async double-buffered NT GEMM core: C[128][128] = A[128,1024]*B[128,1024]^T
// 8 warps = 2(M) x 4(N), warp tile 64x32, BK=32.
// As/Bs: 2 buffers x 128 rows x 40 (pad) bf16 = 20KB each operand.
// ---------------------------------------------------------------------------
__device__ __forceinline__ void gemm_core(const bf16* __restrict__ A,
                                          const bf16* __restrict__ B,
                                          bf16* As, bf16* Bs, float acc[4][4][4])
{
    const int tid = threadIdx.x;
    const int warp = tid >> 5, lane = tid & 31;
    const int gID = lane >> 2, tig = lane & 3;
    const int wm = warp >> 2, wn = warp & 3;

    const uint32_t sA = (uint32_t)__cvta_generic_to_shared(As);
    const uint32_t sB = (uint32_t)__cvta_generic_to_shared(Bs);
    const int crow = tid >> 2, ccol = (tid & 3) * 8;   // copy slot

    auto issue = [&](int buf, int k0) {
        size_t go = (size_t)crow * DD + k0 + ccol;
        uint32_t so = (uint32_t)buf * (128 * 40 * 2) + crow * 80 + ccol * 2;
        CP16(sA + so, A + go);
        CP16(sB + so, B + go);
        go += (size_t)64 * DD;
        so += 64 * 80;
        CP16(sA + so, A + go);
        CP16(sB + so, B + go);
    };

    issue(0, 0);
    CPCOMMIT();

    for (int kt = 0; kt < DD / 32; kt++) {
        if (kt + 1 < DD / 32) { issue((kt + 1) & 1, (kt + 1) * 32); CPCOMMIT(); CPWAIT(1); }
        else                  { CPWAIT(0); }
        __syncthreads();
        const bf16* Ab = As + (kt & 1) * 128 * 40;
        const bf16* Bb = Bs + (kt & 1) * 128 * 40;
        #pragma unroll
        for (int kc = 0; kc < 32; kc += 16) {
            uint32_t a[4][4], b[4][2];
            #pragma unroll
            for (int mt = 0; mt < 4; mt++) {
                int base = wm * 64 + mt * 16;
                a[mt][0] = *(const uint32_t*)&Ab[(base + gID    )*40 + kc +     2*tig];
                a[mt][1] = *(const uint32_t*)&Ab[(base + 8 + gID)*40 + kc +     2*tig];
                a[mt][2] = *(const uint32_t*)&Ab[(base + gID    )*40 + kc + 8 + 2*tig];
                a[mt][3] = *(const uint32_t*)&Ab[(base + 8 + gID)*40 + kc + 8 + 2*tig];
            }
            #pragma unroll
            for (int nt = 0; nt < 4; nt++) {
                int row = wn * 32 + nt * 8 + gID;
                b[nt][0] = *(const uint32_t*)&Bb[row*40 + kc +     2*tig];
                b[nt][1] = *(const uint32_t*)&Bb[row*40 + kc + 8 + 2*tig];
            }
            #pragma unroll
            for (int mt = 0; mt < 4; mt++)
                #pragma unroll
                for (int nt = 0; nt < 4; nt++)
                    mma16(acc[mt][nt], a[mt], b[nt]);
        }
        __syncthreads();
    }
}

// ---------------------------------------------------------------------------
// Kernel: Q,K projection -> head-split bf16 [bh][s][64]. grid (32,8,2)
// ---------------------------------------------------------------------------
__global__ __launch_bounds__(256, 2) void qk_gemm(const float* __restrict__ bq,
                                                  const float* __restrict__ bk)
{
    __shared__ bf16 As[2*128*40], Bs[2*128*40];
    const int which = blockIdx.z;
    const bf16* W     = which ? g_wkb : g_wqb;
    const float* bias = which ? bk : bq;
    bf16* out         = which ? g_k : g_q;
    const float scale = which ? 1.0f : 0.125f;

    const int m0 = blockIdx.x * 128;
    const int n0 = blockIdx.y * 128;

    float acc[4][4][4] = {};
    gemm_core(g_xb + (size_t)m0 * DD, W + (size_t)n0 * DD, As, Bs, acc);

    const int tid = threadIdx.x;
    const int warp = tid >> 5, lane = tid & 31;
    const int gID = lane >> 2, tig = lane & 3;
    const int wm = warp >> 2, wn = warp & 3;

    #pragma unroll
    for (int mt = 0; mt < 4; mt++) {
        #pragma unroll
        for (int nt = 0; nt < 4; nt++) {
            int n = n0 + wn * 32 + nt * 8 + 2 * tig;
            int head = n >> 6, d = n & 63;
            float b0 = bias[n], b1 = bias[n + 1];
            #pragma unroll
            for (int half = 0; half < 2; half++) {
                int m = m0 + wm * 64 + mt * 16 + gID + half * 8;
                int bb = m >> 11, s = m & (SS - 1);
                uint32_t p = packbf((acc[mt][nt][half*2+0] + b0) * scale,
                                    (acc[mt][nt][half*2+1] + b1) * scale);
                *(uint32_t*)&out[((size_t)(bb * HH + head) * SS + s) * HD + d] = p;
            }
        }
    }
}

// ---------------------------------------------------------------------------
// Kernel: V projection transposed: C[d][s]. grid (8, 16, B) -> g_vt bf16.
// ---------------------------------------------------------------------------
__global__ __launch_bounds__(256, 2) void v_gemm(const float* __restrict__ bv)
{
    __shared__ bf16 As[2*128*40], Bs[2*128*40];
    const int m0 = blockIdx.x * 128;          // d
    const int n0 = blockIdx.y * 128;          // s
    const int bb = blockIdx.z;

    float acc[4][4][4] = {};
    gemm_core(g_wvb + (size_t)m0 * DD,
              g_xb + ((size_t)bb * SS + n0) * DD, As, Bs, acc);

    const int tid = threadIdx.x;
    const int warp = tid >> 5, lane = tid & 31;
    const int gID = lane >> 2, tig = lane & 3;
    const int wm = warp >> 2, wn = warp & 3;

    #pragma unroll
    for (int mt = 0; mt < 4; mt++) {
        #pragma unroll
        for (int nt = 0; nt < 4; nt++) {
            int s = n0 + wn * 32 + nt * 8 + 2 * tig;
            #pragma unroll
            for (int half = 0; half < 2; half++) {
                int d = m0 + wm * 64 + mt * 16 + gID + half * 8;
                int head = d >> 6;
                float bia = bv[d];
                uint32_t p = packbf(acc[mt][nt][half*2+0] + bia,
                                    acc[mt][nt][half*2+1] + bia);
                *(uint32_t*)&g_vt[((size_t)(bb * HH + head) * HD + (d & 63)) * SS + s] = p;
            }
        }
    }
}

// ---------------------------------------------------------------------------
// Flash attention: q-tile 128, kv-tile 128, cp.async double-buffered K/V.
// 8 warps, warp owns 16 q-rows. grid (16, 32). Dynamic smem 90112 B.
// ---------------------------------------------------------------------------
#define FL_SMEM ((128*72 + 2*128*72 + 2*64*136) * 2)

__global__ __launch_bounds__(256, 1) void flash_attn(const float* __restrict__ extra,
                                                     const float* __restrict__ mask)
{
    extern __shared__ bf16 smb[];
    bf16* Qs = smb;                      // [128][72]
    bf16* Ks = Qs + 128*72;              // 2 x [128][72]  (kv rows x d)
    bf16* Vt = Ks + 2*128*72;            // 2 x [64][136]  (d x kv)

    const int q0 = blockIdx.x * 128;
    const int bh = blockIdx.y;
    const int b  = bh >> 4;
    const int h  = bh & 15;
    const int tid = threadIdx.x;
    const int warp = tid >> 5, lane = tid & 31;
    const int gID = lane >> 2, tig = lane & 3;
    const int mrow = warp * 16;
    const unsigned FULL = 0xffffffffu;

    const bf16* qp  = g_q  + (size_t)bh * SS * HD;
    const bf16* kp  = g_k  + (size_t)bh * SS * HD;
    const bf16* vtp = g_vt + (size_t)bh * HD * SS;

    const uint32_t sK = (uint32_t)__cvta_generic_to_shared(Ks);
    const uint32_t sV = (uint32_t)__cvta_generic_to_shared(Vt);

    auto issueKV = [&](int buf, int k0) {
        #pragma unroll
        for (int r = 0; r < 4; r++) {
            int i = tid + r * 256;
            int krow = i >> 3, kseg = (i & 7) * 8;
            CP16(sK + (uint32_t)buf * (128*72*2) + (krow*72 + kseg)*2,
                 kp + (size_t)(k0 + krow) * HD + kseg);
            int vrow = i >> 4, vseg = (i & 15) * 8;
            CP16(sV + (uint32_t)buf * (64*136*2) + (vrow*136 + vseg)*2,
                 vtp + (size_t)vrow * SS + k0 + vseg);
        }
    };

    issueKV(0, 0);
    CPCOMMIT();

    // Q tile 128x64 (plain loads, overlap with first cp.async)
    #pragma unroll
    for (int r = 0; r < 4; r++) {
        int c = tid + r * 256;
        int row = c >> 3, seg = (c & 7) * 8;
        *(uint4*)&Qs[row*72 + seg] = *(const uint4*)&qp[(size_t)(q0 + row) * HD + seg];
    }

    float m_run[2] = {-INFINITY, -INFINITY};
    float l_run[2] = {0.f, 0.f};
    float o[8][4] = {};
    const int q_r0 = q0 + mrow + gID;

    for (int kt = 0; kt < SS / 128; kt++) {
        const int k0 = kt * 128;
        if (kt + 1 < SS / 128) { issueKV((kt + 1) & 1, k0 + 128); CPCOMMIT(); CPWAIT(1); }
        else                   { CPWAIT(0); }
        __syncthreads();
        const bf16* Kb = Ks + (kt & 1) * 128*72;
        const bf16* Vb = Vt + (kt & 1) * 64*136;

        // S = Q K^T  (warp 16 x 128, contraction d=64)
        float s[16][4] = {};
        #pragma unroll
        for (int kc = 0; kc < 64; kc += 16) {
            uint32_t a[4];
            a[0] = *(const uint32_t*)&Qs[(mrow + gID    )*72 + kc +     2*tig];
            a[1] = *(const uint32_t*)&Qs[(mrow + 8 + gID)*72 + kc +     2*tig];
            a[2] = *(const uint32_t*)&Qs[(mrow + gID    )*72 + kc + 8 + 2*tig];
            a[3] = *(const uint32_t*)&Qs[(mrow + 8 + gID)*72 + kc + 8 + 2*tig];
            #pragma unroll
            for (int nt = 0; nt < 16; nt++) {
                uint32_t bfr[2];
                bfr[0] = *(const uint32_t*)&Kb[(nt*8 + gID)*72 + kc +     2*tig];
                bfr[1] = *(const uint32_t*)&Kb[(nt*8 + gID)*72 + kc + 8 + 2*tig];
                mma16(s[nt], a, bfr);
            }
        }

        // add extra + mask; online softmax (rows gID, gID+8)
        const float* ep0 = extra + ((size_t)bh * SS + q_r0) * SS + k0;
        const float* ep1 = ep0 + (size_t)8 * SS;
        const float* mp0 = mask + ((size_t)b * SS + q_r0) * SS + k0;
        const float* mp1 = mp0 + (size_t)8 * SS;

        float mx0 = -INFINITY, mx1 = -INFINITY;
        #pragma unroll
        for (int nt = 0; nt < 16; nt++) {
            int c = nt * 8 + 2 * tig;
            float2 e0 = *(const float2*)&ep0[c];
            float2 e1 = *(const float2*)&ep1[c];
            float2 m0v = *(const float2*)&mp0[c];
            float2 m1v = *(const float2*)&mp1[c];
            s[nt][0] += e0.x + m0v.x;  s[nt][1] += e0.y + m0v.y;
            s[nt][2] += e1.x + m1v.x;  s[nt][3] += e1.y + m1v.y;
            mx0 = fmaxf(mx0, fmaxf(s[nt][0], s[nt][1]));
            mx1 = fmaxf(mx1, fmaxf(s[nt][2], s[nt][3]));
        }
        mx0 = fmaxf(mx0, __shfl_xor_sync(FULL, mx0, 1));
        mx0 = fmaxf(mx0, __shfl_xor_sync(FULL, mx0, 2));
        mx1 = fmaxf(mx1, __shfl_xor_sync(FULL, mx1, 1));
        mx1 = fmaxf(mx1, __shfl_xor_sync(FULL, mx1, 2));

        float mn0 = fmaxf(m_run[0], mx0);
        float mn1 = fmaxf(m_run[1], mx1);
        float corr0 = __expf(m_run[0] - mn0);
        float corr1 = __expf(m_run[1] - mn1);
        float ls0 = 0.f, ls1 = 0.f;
        #pragma unroll
        for (int nt = 0; nt < 16; nt++) {
            s[nt][0] = __expf(s[nt][0] - mn0);
            s[nt][1] = __expf(s[nt][1] - mn0);
            s[nt][2] = __expf(s[nt][2] - mn1);
            s[nt][3] = __expf(s[nt][3] - mn1);
            ls0 += s[nt][0] + s[nt][1];
            ls1 += s[nt][2] + s[nt][3];
        }
        ls0 += __shfl_xor_sync(FULL, ls0, 1);
        ls0 += __shfl_xor_sync(FULL, ls0, 2);
        ls1 += __shfl_xor_sync(FULL, ls1, 1);
        ls1 += __shfl_xor_sync(FULL, ls1, 2);
        l_run[0] = l_run[0] * corr0 + ls0;
        l_run[1] = l_run[1] * corr1 + ls1;
        m_run[0] = mn0;  m_run[1] = mn1;

        #pragma unroll
        for (int nt = 0; nt < 8; nt++) {
            o[nt][0] *= corr0;  o[nt][1] *= corr0;
            o[nt][2] *= corr1;  o[nt][3] *= corr1;
        }

        // O += P @ V   (contraction kv=128, P from score fragments)
        #pragma unroll
        for (int t = 0; t < 8; t++) {
            uint32_t a[4];
            a[0] = packbf(s[2*t    ][0], s[2*t    ][1]);
            a[1] = packbf(s[2*t    ][2], s[2*t    ][3]);
            a[2] = packbf(s[2*t + 1][0], s[2*t + 1][1]);
            a[3] = packbf(s[2*t + 1][2], s[2*t + 1][3]);
            #pragma unroll
            for (int nt = 0; nt < 8; nt++) {
                uint32_t bfr[2];
                bfr[0] = *(const uint32_t*)&Vb[(nt*8 + gID)*136 + t*16 +     2*tig];
                bfr[1] = *(const uint32_t*)&Vb[(nt*8 + gID)*136 + t*16 + 8 + 2*tig];
                mma16(o[nt], a, bfr);
            }
        }
        __syncthreads();
    }

    // write ctx bf16 [m][D]
    float inv0 = 1.0f / l_run[0];
    float inv1 = 1.0f / l_run[1];
    #pragma unroll
    for (int nt = 0; nt < 8; nt++) {
        int c = nt * 8 + 2 * tig;
        size_t base0 = ((size_t)(b * SS + q_r0    )) * DD + h * 64 + c;
        size_t base1 = ((size_t)(b * SS + q_r0 + 8)) * DD + h * 64 + c;
        *(uint32_t*)&g_ctx[base0] = packbf(o[nt][0] * inv0, o[nt][1] * inv0);
        *(uint32_t*)&g_ctx[base1] = packbf(o[nt][2] * inv1, o[nt][3] * inv1);
    }
}

// ---------------------------------------------------------------------------
// Output projection. grid (32, 8). fp32 out.
// ---------------------------------------------------------------------------
__global__ __launch_bounds__(256, 2) void out_proj(const float* __restrict__ bo)
{
    __shared__ bf16 As[2*128*40], Bs[2*128*40];
    const int m0 = blockIdx.x * 128;
    const int n0 = blockIdx.y * 128;

    float acc[4][4][4] = {};
    gemm_core(g_ctx + (size_t)m0 * DD, g_wob + (size_t)n0 * DD, As, Bs, acc);

    const int tid = threadIdx.x;
    const int warp = tid >> 5, lane = tid & 31;
    const int gID = lane >> 2, tig = lane & 3;
    const int wm = warp >> 2, wn = warp & 3;

    #pragma unroll
    for (int mt = 0; mt < 4; mt++) {
        #pragma unroll
        for (int nt = 0; nt < 4; nt++) {
            int n = n0 + wn * 32 + nt * 8 + 2 * tig;
            float b0 = bo[n], b1 = bo[n + 1];
            #pragma unroll
            for (int half = 0; half < 2; half++) {
                int m = m0 + wm * 64 + mt * 16 + gID + half * 8;
                float2 v;
                v.x = acc[mt][nt][half*2+0] + b0;
                v.y = acc[mt][nt][half*2+1] + b1;
                *(float2*)&g_attnout[(size_t)m * DD + n] = v;
            }
        }
    }
}

// ---------------------------------------------------------------------------
// residual + LayerNorm
// ---------------------------------------------------------------------------
__global__ void resid_ln(const float* __restrict__ hid,
                         const float* __restrict__ gamma,
                         const float* __restrict__ beta,
                         float* __restrict__ out)
{
    const int m = blockIdx.x;
    const int tid = threadIdx.x;
    const unsigned FULL = 0xffffffffu;

    float x[4];
    float sum = 0.f, sumsq = 0.f;
    #pragma unroll
    for (int r = 0; r < 4; r++) {
        int i = tid + r * 256;
        x[r] = hid[(size_t)m * DD + i] + g_attnout[(size_t)m * DD + i];
        sum += x[r];
        sumsq += x[r] * x[r];
    }
    #pragma unroll
    for (int off = 16; off > 0; off >>= 1) {
        sum   += __shfl_xor_sync(FULL, sum,   off);
        sumsq += __shfl_xor_sync(FULL, sumsq, off);
    }
    __shared__ float sh[2][8];
    int wid = tid >> 5, lane = tid & 31;
    if (lane == 0) { sh[0][wid] = sum; sh[1][wid] = sumsq; }
    __syncthreads();
    if (tid == 0) {
        float a = 0.f, c = 0.f;
        #pragma unroll
        for (int w = 0; w < 8; w++) { a += sh[0][w]; c += sh[1][w]; }
        sh[0][0] = a; sh[1][0] = c;
    }
    __syncthreads();
    float mu  = sh[0][0] * (1.0f / DD);
    float var = sh[1][0] * (1.0f / DD) - mu * mu;
    float inv = rsqrtf(var + LN_EPS);
    #pragma unroll
    for (int r = 0; r < 4; r++) {
        int i = tid + r * 256;
        out[(size_t)m * DD + i] = (x[r] - mu) * inv * gamma[i] + beta[i];
    }
}

// ---------------------------------------------------------------------------
extern "C" void kernel_launch(void* const* d_in, const int* in_sizes, int n_in,
                              void* d_out, int out_size)
{
    const float* hid   = (const float*)d_in[0];
    const float* mask  = (const float*)d_in[1];
    const float* extra = (const float*)d_in[2];
    const float* Wq = (const float*)d_in[3];  const float* bq = (const float*)d_in[4];
    const float* Wk = (const float*)d_in[5];  const float* bk = (const float*)d_in[6];
    const float* Wv = (const float*)d_in[7];  const float* bv = (const float*)d_in[8];
    const float* Wo = (const float*)d_in[9];  const float* bo = (const float*)d_in[10];
    const float* gamma = (const float*)d_in[11];
    const float* beta  = (const float*)d_in[12];
    float* out = (float*)d_out;

    bf16 *d_xb, *d_wqb, *d_wkb, *d_wvb, *d_wob;
    cudaGetSymbolAddress((void**)&d_xb,  g_xb);
    cudaGetSymbolAddress((void**)&d_wqb, g_wqb);
    cudaGetSymbolAddress((void**)&d_wkb, g_wkb);
    cudaGetSymbolAddress((void**)&d_wvb, g_wvb);
    cudaGetSymbolAddress((void**)&d_wob, g_wob);

    cudaFuncSetAttribute(flash_attn, cudaFuncAttributeMaxDynamicSharedMemorySize,
                         FL_SMEM);

    // launch order puts flash_attn at index 5 for ncu -s 5 -c 1
    conv_x <<<1024, 256>>>(hid, d_xb, MTOT*DD/4);                 // 0
    conv_w2<<<1024, 256>>>(Wq, Wk, d_wqb, d_wkb);                 // 1
    conv_w2<<<1024, 256>>>(Wv, Wo, d_wvb, d_wob);                 // 2
    qk_gemm<<<dim3(MTOT/128, DD/128, 2), 256>>>(bq, bk);          // 3
    v_gemm <<<dim3(DD/128, SS/128, BB), 256>>>(bv);               // 4
    flash_attn<<<dim3(SS/128, BHT), 256, FL_SMEM>>>(extra, mask); // 5
    out_proj<<<dim3(MTOT/128, DD/128), 256>>>(bo);                // 6
    resid_ln<<<MTOT, 256>>>(hid, gamma, beta, out);               // 7
}

// round 7
// speedup vs baseline: 9.2512x; 1.0786x over previous
#include <cuda_runtime.h>
#include <cuda_bf16.h>
#include <math.h>
#include <stdint.h>

#define BB 2
#define SS 2048
#define DD 1024
#define HH 16
#define HD 64
#define MTOT (BB*SS)   // 4096
#define BHT (BB*HH)    // 32
#define LN_EPS 1e-5f

typedef __nv_bfloat16 bf16;
typedef __nv_bfloat162 bf162;

// ---------------- global bf16 scratch (allocation-free rule) ---------------
__device__ bf16 g_xb [(size_t)MTOT*DD];
__device__ bf16 g_wqb[(size_t)DD*DD];
__device__ bf16 g_wkb[(size_t)DD*DD];
__device__ bf16 g_wvb[(size_t)DD*DD];
__device__ bf16 g_wob[(size_t)DD*DD];
__device__ bf16 g_q  [(size_t)BHT*SS*HD];   // [bh][s][d]
__device__ bf16 g_k  [(size_t)BHT*SS*HD];   // [bh][s][d]
__device__ bf16 g_vt [(size_t)BHT*HD*SS];   // [bh][d][s]  transposed
__device__ bf16 g_ctx[(size_t)MTOT*DD];     // [m][D]
__device__ float g_attnout[(size_t)MTOT*DD];

#define CP16(dst, src) asm volatile("cp.async.ca.shared.global [%0], [%1], 16;" :: "r"(dst), "l"(src))
#define CPCOMMIT()     asm volatile("cp.async.commit_group;")
#define CPWAIT(N)      asm volatile("cp.async.wait_group %0;" :: "n"(N))

__device__ __forceinline__ uint32_t packbf(float lo, float hi) {
    bf162 h;
    h.x = __float2bfloat16_rn(lo);
    h.y = __float2bfloat16_rn(hi);
    return *(uint32_t*)&h;
}
__device__ __forceinline__ void mma16(float c[4], const uint32_t a[4], const uint32_t b[2]) {
    asm volatile("mma.sync.aligned.m16n8k16.row.col.f32.bf16.bf16.f32 "
                 "{%0,%1,%2,%3},{%4,%5,%6,%7},{%8,%9},{%0,%1,%2,%3};"
                 : "+f"(c[0]), "+f"(c[1]), "+f"(c[2]), "+f"(c[3])
                 : "r"(a[0]), "r"(a[1]), "r"(a[2]), "r"(a[3]),
                   "r"(b[0]), "r"(b[1]));
}
__device__ __forceinline__ void ldsm4(uint32_t r[4], uint32_t addr) {
    asm volatile("ldmatrix.sync.aligned.m8n8.x4.shared.b16 {%0,%1,%2,%3}, [%4];"
                 : "=r"(r[0]), "=r"(r[1]), "=r"(r[2]), "=r"(r[3]) : "r"(addr));
}

// Fast exp on the FMA pipe (no MUFU). x <= 0 expected; accurate to ~4e-5 rel.
__device__ __forceinline__ float fexp(float x) {
    float y = fmaxf(x * 1.4426950408889634f, -126.0f);
    float z = y + 12582912.0f;            // round-to-nearest via magic
    float n = z - 12582912.0f;
    float f = y - n;
    float p =      0.00961812910f;        // 2^f Taylor deg-4, |f|<=0.5
    p = fmaf(p, f, 0.05550410866f);
    p = fmaf(p, f, 0.24022650696f);
    p = fmaf(p, f, 0.69314718056f);
    p = fmaf(p, f, 1.0f);
    uint32_t sb = (uint32_t)(__float_as_int(z) - 0x4B400000 + 127) << 23;
    return p * __uint_as_float(sb);
}

// ---------------------------------------------------------------------------
// Converts
// ---------------------------------------------------------------------------
__global__ void conv_x(const float* __restrict__ src, bf16* __restrict__ dst, int n4)
{
    int i = blockIdx.x * blockDim.x + threadIdx.x;
    int stride = gridDim.x * blockDim.x;
    for (; i < n4; i += stride) {
        float4 x = ((const float4*)src)[i];
        uint2 o;
        o.x = packbf(x.x, x.y);
        o.y = packbf(x.z, x.w);
        ((uint2*)dst)[i] = o;
    }
}
__global__ void conv_w2(const float* __restrict__ s0, const float* __restrict__ s1,
                        bf16* __restrict__ d0, bf16* __restrict__ d1)
{
    const int n4 = DD * DD / 4;
    int i = blockIdx.x * blockDim.x + threadIdx.x;
    int stride = gridDim.x * blockDim.x;
    for (; i < 2 * n4; i += stride) {
        const float4 x = (i < n4) ? ((const float4*)s0)[i] : ((const float4*)s1)[i - n4];
        uint2 o;
        o.x = packbf(x.x, x.y);
        o.y = packbf(x.z, x.w);
        if (i < n4) ((uint2*)d0)[i] = o; else ((uint2*)d1)[i - n4] = o;
    }
}

// ---------------------------------------------------------------------------
// cp.async double-buffered NT GEMM core with ldmatrix fragment loads.
// C[128][128] = A[128,1024] * B[128,1024]^T. 8 warps = 2(M) x 4(N),
// warp tile 64x32, BK=32. Buffers: 2 x 128 x 40 bf16 per operand.
// ---------------------------------------------------------------------------
__device__ __forceinline__ void gemm_core(const bf16* __restrict__ A,
                                          const bf16* __restrict__ B,
                                          bf16* As, bf16* Bs, float acc[4][4][4])
{
    const int tid = threadIdx.x;
    const int warp = tid >> 5, lane = tid & 31;
    const int wm = warp >> 2, wn = warp & 3;
    const int mat = lane >> 3, li = lane & 7;
    const int rofA = ((mat & 1) << 3) + li;       // A-matrix row offset
    const int cofA = (mat >> 1) << 3;             // A-matrix col offset
    const int rofB = ((mat >> 1) << 3) + li;      // B row-within-pair
    const int cofB = (mat & 1) << 3;              // B col offset

    const uint32_t sA = (uint32_t)__cvta_generic_to_shared(As);
    const uint32_t sB = (uint32_t)__cvta_generic_to_shared(Bs);
    const int crow = tid >> 2, ccol = (tid & 3) * 8;   // copy slot

    auto issue = [&](int buf, int k0) {
        size_t go = (size_t)crow * DD + k0 + ccol;
        uint32_t so = (uint32_t)buf * (128 * 40 * 2) + crow * 80 + ccol * 2;
        CP16(sA + so, A + go);
        CP16(sB + so, B + go);
        go += (size_t)64 * DD;
        so += 64 * 80;
        CP16(sA + so, A + go);
        CP16(sB + so, B + go);
    };

    issue(0, 0);
    CPCOMMIT();

    for (int kt = 0; kt < DD / 32; kt++) {
        if (kt + 1 < DD / 32) { issue((kt + 1) & 1, (kt + 1) * 32); CPCOMMIT(); CPWAIT(1); }
        else                  { CPWAIT(0); }
        __syncthreads();
        const uint32_t abase = sA + (kt & 1) * (128 * 80) + (wm * 64 + rofA) * 80 + cofA * 2;
        const uint32_t bbase = sB + (kt & 1) * (128 * 80) + (wn * 32 + rofB) * 80 + cofB * 2;
        #pragma unroll
        for (int kc = 0; kc < 32; kc += 16) {
            uint32_t a[4][4], b[2][4];
            #pragma unroll
            for (int mt = 0; mt < 4; mt++)
                ldsm4(a[mt], abase + mt * (16 * 80) + kc * 2);
            #pragma unroll
            for (int pr = 0; pr < 2; pr++)
                ldsm4(b[pr], bbase + pr * (16 * 80) + kc * 2);
            #pragma unroll
            for (int mt = 0; mt < 4; mt++)
                #pragma unroll
                for (int pr = 0; pr < 2; pr++) {
                    mma16(acc[mt][2*pr    ], a[mt], &b[pr][0]);
                    mma16(acc[mt][2*pr + 1], a[mt], &b[pr][2]);
                }
        }
        __syncthreads();
    }
}

// ---------------------------------------------------------------------------
// Q,K projection -> head-split bf16 [bh][s][64]. grid (32,8,2)
// ---------------------------------------------------------------------------
__global__ __launch_bounds__(256, 2) void qk_gemm(const float* __restrict__ bq,
                                                  const float* __restrict__ bk)
{
    __shared__ bf16 As[2*128*40], Bs[2*128*40];
    const int which = blockIdx.z;
    const bf16* W     = which ? g_wkb : g_wqb;
    const float* bias = which ? bk : bq;
    bf16* out         = which ? g_k : g_q;
    const float scale = which ? 1.0f : 0.125f;

    const int m0 = blockIdx.x * 128;
    const int n0 = blockIdx.y * 128;

    float acc[4][4][4] = {};
    gemm_core(g_xb + (size_t)m0 * DD, W + (size_t)n0 * DD, As, Bs, acc);

    const int tid = threadIdx.x;
    const int warp = tid >> 5, lane = tid & 31;
    const int gID = lane >> 2, tig = lane & 3;
    const int wm = warp >> 2, wn = warp & 3;

    #pragma unroll
    for (int mt = 0; mt < 4; mt++) {
        #pragma unroll
        for (int nt = 0; nt < 4; nt++) {
            int n = n0 + wn * 32 + nt * 8 + 2 * tig;
            int head = n >> 6, d = n & 63;
            float b0 = bias[n], b1 = bias[n + 1];
            #pragma unroll
            for (int half = 0; half < 2; half++) {
                int m = m0 + wm * 64 + mt * 16 + gID + half * 8;
                int bb = m >> 11, s = m & (SS - 1);
                uint32_t p = packbf((acc[mt][nt][half*2+0] + b0) * scale,
                                    (acc[mt][nt][half*2+1] + b1) * scale);
                *(uint32_t*)&out[((size_t)(bb * HH + head) * SS + s) * HD + d] = p;
            }
        }
    }
}

// ---------------------------------------------------------------------------
// V projection transposed: C[d][s]. grid (8, 16, B) -> g_vt bf16.
// ---------------------------------------------------------------------------
__global__ __launch_bounds__(256, 2) void v_gemm(const float* __restrict__ bv)
{
    __shared__ bf16 As[2*128*40], Bs[2*128*40];
    const int m0 = blockIdx.x * 128;          // d
    const int n0 = blockIdx.y * 128;          // s
    const int bb = blockIdx.z;

    float acc[4][4][4] = {};
    gemm_core(g_wvb + (size_t)m0 * DD,
              g_xb + ((size_t)bb * SS + n0) * DD, As, Bs, acc);

    const int tid = threadIdx.x;
    const int warp = tid >> 5, lane = tid & 31;
    const int gID = lane >> 2, tig = lane & 3;
    const int wm = warp >> 2, wn = warp & 3;

    #pragma unroll
    for (int mt = 0; mt < 4; mt++) {
        #pragma unroll
        for (int nt = 0; nt < 4; nt++) {
            int s = n0 + wn * 32 + nt * 8 + 2 * tig;
            #pragma unroll
            for (int half = 0; half < 2; half++) {
                int d = m0 + wm * 64 + mt * 16 + gID + half * 8;
                int head = d >> 6;
                float bia = bv[d];
                uint32_t p = packbf(acc[mt][nt][half*2+0] + bia,
                                    acc[mt][nt][half*2+1] + bia);
                *(uint32_t*)&g_vt[((size_t)(bb * HH + head) * HD + (d & 63)) * SS + s] = p;
            }
        }
    }
}

// ---------------------------------------------------------------------------
// Flash attention: q-tile 128, kv-tile 128, cp.async double-buffered K/V,
// ldmatrix fragments, FMA-pipe exp. 8 warps, warp owns 16 q-rows. grid (16,32).
// ---------------------------------------------------------------------------
#define FL_SMEM ((128*72 + 2*128*72 + 2*64*136) * 2)

__global__ __launch_bounds__(256, 1) void flash_attn(const float* __restrict__ extra,
                                                     const float* __restrict__ mask)
{
    extern __shared__ bf16 smb[];
    bf16* Qs = smb;                      // [128][72]
    bf16* Ks = Qs + 128*72;              // 2 x [128][72]  (kv rows x d)
    bf16* Vt = Ks + 2*128*72;            // 2 x [64][136]  (d x kv)

    const int q0 = blockIdx.x * 128;
    const int bh = blockIdx.y;
    const int b  = bh >> 4;
    const int h  = bh & 15;
    const int tid = threadIdx.x;
    const int warp = tid >> 5, lane = tid & 31;
    const int gID = lane >> 2, tig = lane & 3;
    const int mrow = warp * 16;
    const int mat = lane >> 3, li = lane & 7;
    const int rofA = ((mat & 1) << 3) + li;     // A-frag row offset
    const int cofA = (mat >> 1) << 3;
    const int rofB = ((mat >> 1) << 3) + li;    // B-frag row-within-pair
    const int cofB = (mat & 1) << 3;
    const unsigned FULL = 0xffffffffu;

    const bf16* qp  = g_q  + (size_t)bh * SS * HD;
    const bf16* kp  = g_k  + (size_t)bh * SS * HD;
    const bf16* vtp = g_vt + (size_t)bh * HD * SS;

    const uint32_t sQ = (uint32_t)__cvta_generic_to_shared(Qs);
    const uint32_t sK = (uint32_t)__cvta_generic_to_shared(Ks);
    const uint32_t sV = (uint32_t)__cvta_generic_to_shared(Vt);

    auto issueKV = [&](int buf, int k0) {
        #pragma unroll
        for (int r = 0; r < 4; r++) {
            int i = tid + r * 256;
            int krow = i >> 3, kseg = (i & 7) * 8;
            CP16(sK + (uint32_t)buf * (128*72*2) + (krow*72 + kseg)*2,
                 kp + (size_t)(k0 + krow) * HD + kseg);
            int vrow = i >> 4, vseg = (i & 15) * 8;
            CP16(sV + (uint32_t)buf * (64*136*2) + (vrow*136 + vseg)*2,
                 vtp + (size_t)vrow * SS + k0 + vseg);
        }
    };

    issueKV(0, 0);
    CPCOMMIT();

    // Q tile 128x64 (plain loads overlap first cp.async)
    #pragma unroll
    for (int r = 0; r < 4; r++) {
        int c = tid + r * 256;
        int row = c >> 3, seg = (c & 7) * 8;
        *(uint4*)&Qs[row*72 + seg] = *(const uint4*)&qp[(size_t)(q0 + row) * HD + seg];
    }
    __syncthreads();

    // Hoist Q fragments into registers (4 kc-chunks x 4 regs)
    uint32_t qf[4][4];
    {
        uint32_t qbase = sQ + (mrow + rofA) * 144 + cofA * 2;
        #pragma unroll
        for (int c4 = 0; c4 < 4; c4++)
            ldsm4(qf[c4], qbase + c4 * 32);
    }

    float m_run[2] = {-INFINITY, -INFINITY};
    float l_run[2] = {0.f, 0.f};
    float o[8][4] = {};
    const int q_r0 = q0 + mrow + gID;

    for (int kt = 0; kt < SS / 128; kt++) {
        const int k0 = kt * 128;
        if (kt + 1 < SS / 128) { issueKV((kt + 1) & 1, k0 + 128); CPCOMMIT(); CPWAIT(1); }
        else                   { CPWAIT(0); }
        __syncthreads();
        const uint32_t kb = sK + (kt & 1) * (128*72*2) + rofB * 144 + cofB * 2;
        const uint32_t vb = sV + (kt & 1) * (64*136*2) + rofB * 272 + cofB * 2;

        // S = Q K^T  (warp 16 x 128, contraction d=64)
        float s[16][4] = {};
        #pragma unroll
        for (int c4 = 0; c4 < 4; c4++) {
            #pragma unroll
            for (int pr = 0; pr < 8; pr++) {
                uint32_t kf[4];
                ldsm4(kf, kb + pr * (16 * 144) + c4 * 32);
                mma16(s[2*pr    ], qf[c4], &kf[0]);
                mma16(s[2*pr + 1], qf[c4], &kf[2]);
            }
        }

        // add extra + mask; online softmax (rows gID, gID+8)
        const float* ep0 = extra + ((size_t)bh * SS + q_r0) * SS + k0;
        const float* ep1 = ep0 + (size_t)8 * SS;
        const float* mp0 = mask + ((size_t)b * SS + q_r0) * SS + k0;
        const float* mp1 = mp0 + (size_t)8 * SS;

        float mx0 = -INFINITY, mx1 = -INFINITY;
        #pragma unroll
        for (int nt = 0; nt < 16; nt++) {
            int c = nt * 8 + 2 * tig;
            float2 e0 = *(const float2*)&ep0[c];
            float2 e1 = *(const float2*)&ep1[c];
            float2 m0v = *(const float2*)&mp0[c];
            float2 m1v = *(const float2*)&mp1[c];
            s[nt][0] += e0.x + m0v.x;  s[nt][1] += e0.y + m0v.y;
            s[nt][2] += e1.x + m1v.x;  s[nt][3] += e1.y + m1v.y;
            mx0 = fmaxf(mx0, fmaxf(s[nt][0], s[nt][1]));
            mx1 = fmaxf(mx1, fmaxf(s[nt][2], s[nt][3]));
        }
        mx0 = fmaxf(mx0, __shfl_xor_sync(FULL, mx0, 1));
        mx0 = fmaxf(mx0, __shfl_xor_sync(FULL, mx0, 2));
        mx1 = fmaxf(mx1, __shfl_xor_sync(FULL, mx1, 1));
        mx1 = fmaxf(mx1, __shfl_xor_sync(FULL, mx1, 2));

        float mn0 = fmaxf(m_run[0], mx0);
        float mn1 = fmaxf(m_run[1], mx1);
        float corr0 = fexp(m_run[0] - mn0);
        float corr1 = fexp(m_run[1] - mn1);
        float ls0 = 0.f, ls1 = 0.f;
        #pragma unroll
        for (int nt = 0; nt < 16; nt++) {
            s[nt][0] = fexp(s[nt][0] - mn0);
            s[nt][1] = fexp(s[nt][1] - mn0);
            s[nt][2] = fexp(s[nt][2] - mn1);
            s[nt][3] = fexp(s[nt][3] - mn1);
            ls0 += s[nt][0] + s[nt][1];
            ls1 += s[nt][2] + s[nt][3];
        }
        ls0 += __shfl_xor_sync(FULL, ls0, 1);
        ls0 += __shfl_xor_sync(FULL, ls0, 2);
        ls1 += __shfl_xor_sync(FULL, ls1, 1);
        ls1 += __shfl_xor_sync(FULL, ls1, 2);
        l_run[0] = l_run[0] * corr0 + ls0;
        l_run[1] = l_run[1] * corr1 + ls1;
        m_run[0] = mn0;  m_run[1] = mn1;

        #pragma unroll
        for (int nt = 0; nt < 8; nt++) {
            o[nt][0] *= corr0;  o[nt][1] *= corr0;
            o[nt][2] *= corr1;  o[nt][3] *= corr1;
        }

        // O += P @ V   (contraction kv=128, P packed from score fragments)
        #pragma unroll
        for (int t = 0; t < 8; t++) {
            uint32_t a[4];
            a[0] = packbf(s[2*t    ][0], s[2*t    ][1]);
            a[1] = packbf(s[2*t    ][2], s[2*t    ][3]);
            a[2] = packbf(s[2*t + 1][0], s[2*t + 1][1]);
            a[3] = packbf(s[2*t + 1][2], s[2*t + 1][3]);
            #pragma unroll
            for (int pr = 0; pr < 4; pr++) {
                uint32_t vf[4];
                ldsm4(vf, vb + pr * (16 * 272) + t * 32);
                mma16(o[2*pr    ], a, &vf[0]);
                mma16(o[2*pr + 1], a, &vf[2]);
            }
        }
        __syncthreads();
    }

    // write ctx bf16 [m][D]
    float inv0 = 1.0f / l_run[0];
    float inv1 = 1.0f / l_run[1];
    #pragma unroll
    for (int nt = 0; nt < 8; nt++) {
        int c = nt * 8 + 2 * tig;
        size_t base0 = ((size_t)(b * SS + q_r0    )) * DD + h * 64 + c;
        size_t base1 = ((size_t)(b * SS + q_r0 + 8)) * DD + h * 64 + c;
        *(uint32_t*)&g_ctx[base0] = packbf(o[nt][0] * inv0, o[nt][1] * inv0);
        *(uint32_t*)&g_ctx[base1] = packbf(o[nt][2] * inv1, o[nt][3] * inv1);
    }
}

// ---------------------------------------------------------------------------
// Output projection. grid (32, 8). fp32 out.
// ---------------------------------------------------------------------------
__global__ __launch_bounds__(256, 2) void out_proj(const float* __restrict__ bo)
{
    __shared__ bf16 As[2*128*40], Bs[2*128*40];
    const int m0 = blockIdx.x * 128;
    const int n0 = blockIdx.y * 128;

    float acc[4][4][4] = {};
    gemm_core(g_ctx + (size_t)m0 * DD, g_wob + (size_t)n0 * DD, As, Bs, acc);

    const int tid = threadIdx.x;
    const int warp = tid >> 5, lane = tid & 31;
    const int gID = lane >> 2, tig = lane & 3;
    const int wm = warp >> 2, wn = warp & 3;

    #pragma unroll
    for (int mt = 0; mt < 4; mt++) {
        #pragma unroll
        for (int nt = 0; nt < 4; nt++) {
            int n = n0 + wn * 32 + nt * 8 + 2 * tig;
            float b0 = bo[n], b1 = bo[n + 1];
            #pragma unroll
            for (int half = 0; half < 2; half++) {
                int m = m0 + wm * 64 + mt * 16 + gID + half * 8;
                float2 v;
                v.x = acc[mt][nt][half*2+0] + b0;
                v.y = acc[mt][nt][half*2+1] + b1;
                *(float2*)&g_attnout[(size_t)m * DD + n] = v;
            }
        }
    }
}

// ---------------------------------------------------------------------------
// residual + LayerNorm
// ---------------------------------------------------------------------------
__global__ void resid_ln(const float* __restrict__ hid,
                         const float* __restrict__ gamma,
                         const float* __restrict__ beta,
                         float* __restrict__ out)
{
    const int m = blockIdx.x;
    const int tid = threadIdx.x;
    const unsigned FULL = 0xffffffffu;

    float x[4];
    float sum = 0.f, sumsq = 0.f;
    #pragma unroll
    for (int r = 0; r < 4; r++) {
        int i = tid + r * 256;
        x[r] = hid[(size_t)m * DD + i] + g_attnout[(size_t)m * DD + i];
        sum += x[r];
        sumsq += x[r] * x[r];
    }
    #pragma unroll
    for (int off = 16; off > 0; off >>= 1) {
        sum   += __shfl_xor_sync(FULL, sum,   off);
        sumsq += __shfl_xor_sync(FULL, sumsq, off);
    }
    __shared__ float sh[2][8];
    int wid = tid >> 5, lane = tid & 31;
    if (lane == 0) { sh[0][wid] = sum; sh[1][wid] = sumsq; }
    __syncthreads();
    if (tid == 0) {
        float a = 0.f, c = 0.f;
        #pragma unroll
        for (int w = 0; w < 8; w++) { a += sh[0][w]; c += sh[1][w]; }
        sh[0][0] = a; sh[1][0] = c;
    }
    __syncthreads();
    float mu  = sh[0][0] * (1.0f / DD);
    float var = sh[1][0] * (1.0f / DD) - mu * mu;
    float inv = rsqrtf(var + LN_EPS);
    #pragma unroll
    for (int r = 0; r < 4; r++) {
        int i = tid + r * 256;
        out[(size_t)m * DD + i] = (x[r] - mu) * inv * gamma[i] + beta[i];
    }
}

// ---------------------------------------------------------------------------
extern "C" void kernel_launch(void* const* d_in, const int* in_sizes, int n_in,
                              void* d_out, int out_size)
{
    const float* hid   = (const float*)d_in[0];
    const float* mask  = (const float*)d_in[1];
    const float* extra = (const float*)d_in[2];
    const float* Wq = (const float*)d_in[3];  const float* bq = (const float*)d_in[4];
    const float* Wk = (const float*)d_in[5];  const float* bk = (const float*)d_in[6];
    const float* Wv = (const float*)d_in[7];  const float* bv = (const float*)d_in[8];
    const float* Wo = (const float*)d_in[9];  const float* bo = (const float*)d_in[10];
    const float* gamma = (const float*)d_in[11];
    const float* beta  = (const float*)d_in[12];
    float* out = (float*)d_out;

    bf16 *d_xb, *d_wqb, *d_wkb, *d_wvb, *d_wob;
    cudaGetSymbolAddress((void**)&d_xb,  g_xb);
    cudaGetSymbolAddress((void**)&d_wqb, g_wqb);
    cudaGetSymbolAddress((void**)&d_wkb, g_wkb);
    cudaGetSymbolAddress((void**)&d_wvb, g_wvb);
    cudaGetSymbolAddress((void**)&d_wob, g_wob);

    cudaFuncSetAttribute(flash_attn, cudaFuncAttributeMaxDynamicSharedMemorySize,
                         FL_SMEM);

    // launch order puts flash_attn at index 5 for ncu -s 5 -c 1
    conv_x <<<1024, 256>>>(hid, d_xb, MTOT*DD/4);                 // 0
    conv_w2<<<1024, 256>>>(Wq, Wk, d_wqb, d_wkb);                 // 1
    conv_w2<<<1024, 256>>>(Wv, Wo, d_wvb, d_wob);                 // 2
    qk_gemm<<<dim3(MTOT/128, DD/128, 2), 256>>>(bq, bk);          // 3
    v_gemm <<<dim3(DD/128, SS/128, BB), 256>>>(bv);               // 4
    flash_attn<<<dim3(SS/128, BHT), 256, FL_SMEM>>>(extra, mask); // 5
    out_proj<<<dim3(MTOT/128, DD/128), 256>>>(bo);                // 6
    resid_ln<<<MTOT, 256>>>(hid, gamma, beta, out);               // 7
}

// round 8
// speedup vs baseline: 10.3127x; 1.1147x over previous
#include <cuda_runtime.h>
#include <cuda_bf16.h>
#include <math.h>
#include <stdint.h>

#define BB 2
#define SS 2048
#define DD 1024
#define HH 16
#define HD 64
#define MTOT (BB*SS)   // 4096
#define BHT (BB*HH)    // 32
#define LN_EPS 1e-5f

typedef __nv_bfloat16 bf16;
typedef __nv_bfloat162 bf162;

// ---------------- global bf16 scratch (allocation-free rule) ---------------
__device__ bf16 g_xb [(size_t)MTOT*DD];
__device__ bf16 g_wqb[(size_t)DD*DD];
__device__ bf16 g_wkb[(size_t)DD*DD];
__device__ bf16 g_wvb[(size_t)DD*DD];
__device__ bf16 g_wob[(size_t)DD*DD];
__device__ bf16 g_q  [(size_t)BHT*SS*HD];   // [bh][s][d]
__device__ bf16 g_k  [(size_t)BHT*SS*HD];   // [bh][s][d]
__device__ bf16 g_vt [(size_t)BHT*HD*SS];   // [bh][d][s]  transposed
__device__ bf16 g_ctx[(size_t)MTOT*DD];     // [m][D]
__device__ float g_attnout[(size_t)MTOT*DD];

#define CP16(dst, src) asm volatile("cp.async.ca.shared.global [%0], [%1], 16;" :: "r"(dst), "l"(src))
#define CPCOMMIT()     asm volatile("cp.async.commit_group;")
#define CPWAIT(N)      asm volatile("cp.async.wait_group %0;" :: "n"(N))

__device__ __forceinline__ uint32_t packbf(float lo, float hi) {
    bf162 h;
    h.x = __float2bfloat16_rn(lo);
    h.y = __float2bfloat16_rn(hi);
    return *(uint32_t*)&h;
}
__device__ __forceinline__ void mma16(float c[4], const uint32_t a[4], const uint32_t b[2]) {
    asm volatile("mma.sync.aligned.m16n8k16.row.col.f32.bf16.bf16.f32 "
                 "{%0,%1,%2,%3},{%4,%5,%6,%7},{%8,%9},{%0,%1,%2,%3};"
                 : "+f"(c[0]), "+f"(c[1]), "+f"(c[2]), "+f"(c[3])
                 : "r"(a[0]), "r"(a[1]), "r"(a[2]), "r"(a[3]),
                   "r"(b[0]), "r"(b[1]));
}
__device__ __forceinline__ void ldsm4(uint32_t r[4], uint32_t addr) {
    asm volatile("ldmatrix.sync.aligned.m8n8.x4.shared.b16 {%0,%1,%2,%3}, [%4];"
                 : "=r"(r[0]), "=r"(r[1]), "=r"(r[2]), "=r"(r[3]) : "r"(addr));
}

// Fast exp on the FMA pipe (no MUFU). x <= 0 expected; accurate to ~4e-5 rel.
__device__ __forceinline__ float fexp(float x) {
    float y = fmaxf(x * 1.4426950408889634f, -126.0f);
    float z = y + 12582912.0f;            // round-to-nearest via magic
    float n = z - 12582912.0f;
    float f = y - n;
    float p =      0.00961812910f;        // 2^f Taylor deg-4, |f|<=0.5
    p = fmaf(p, f, 0.05550410866f);
    p = fmaf(p, f, 0.24022650696f);
    p = fmaf(p, f, 0.69314718056f);
    p = fmaf(p, f, 1.0f);
    uint32_t sb = (uint32_t)(__float_as_int(z) - 0x4B400000 + 127) << 23;
    return p * __uint_as_float(sb);
}

// ---------------------------------------------------------------------------
// Converts
// ---------------------------------------------------------------------------
__global__ void conv_x(const float* __restrict__ src, bf16* __restrict__ dst, int n4)
{
    int i = blockIdx.x * blockDim.x + threadIdx.x;
    int stride = gridDim.x * blockDim.x;
    for (; i < n4; i += stride) {
        float4 x = ((const float4*)src)[i];
        uint2 o;
        o.x = packbf(x.x, x.y);
        o.y = packbf(x.z, x.w);
        ((uint2*)dst)[i] = o;
    }
}
__global__ void conv_w2(const float* __restrict__ s0, const float* __restrict__ s1,
                        bf16* __restrict__ d0, bf16* __restrict__ d1)
{
    const int n4 = DD * DD / 4;
    int i = blockIdx.x * blockDim.x + threadIdx.x;
    int stride = gridDim.x * blockDim.x;
    for (; i < 2 * n4; i += stride) {
        const float4 x = (i < n4) ? ((const float4*)s0)[i] : ((const float4*)s1)[i - n4];
        uint2 o;
        o.x = packbf(x.x, x.y);
        o.y = packbf(x.z, x.w);
        if (i < n4) ((uint2*)d0)[i] = o; else ((uint2*)d1)[i - n4] = o;
    }
}

// ---------------------------------------------------------------------------
// cp.async double-buffered NT GEMM core, SINGLE barrier per K-tile:
//   wait -> sync -> issue(next) -> compute.
// C[128][128] = A[128,1024] * B[128,1024]^T. 8 warps = 2(M) x 4(N),
// warp tile 64x32, BK=32.
// ---------------------------------------------------------------------------
__device__ __forceinline__ void gemm_core(const bf16* __restrict__ A,
                                          const bf16* __restrict__ B,
                                          bf16* As, bf16* Bs, float acc[4][4][4])
{
    const int tid = threadIdx.x;
    const int warp = tid >> 5, lane = tid & 31;
    const int wm = warp >> 2, wn = warp & 3;
    const int mat = lane >> 3, li = lane & 7;
    const int rofA = ((mat & 1) << 3) + li;
    const int cofA = (mat >> 1) << 3;
    const int rofB = ((mat >> 1) << 3) + li;
    const int cofB = (mat & 1) << 3;

    const uint32_t sA = (uint32_t)__cvta_generic_to_shared(As);
    const uint32_t sB = (uint32_t)__cvta_generic_to_shared(Bs);
    const int crow = tid >> 2, ccol = (tid & 3) * 8;

    auto issue = [&](int buf, int k0) {
        size_t go = (size_t)crow * DD + k0 + ccol;
        uint32_t so = (uint32_t)buf * (128 * 40 * 2) + crow * 80 + ccol * 2;
        CP16(sA + so, A + go);
        CP16(sB + so, B + go);
        go += (size_t)64 * DD;
        so += 64 * 80;
        CP16(sA + so, A + go);
        CP16(sB + so, B + go);
    };

    issue(0, 0);
    CPCOMMIT();

    for (int kt = 0; kt < DD / 32; kt++) {
        CPWAIT(0);
        __syncthreads();                 // data ready + prior buffer free
        if (kt + 1 < DD / 32) { issue((kt + 1) & 1, (kt + 1) * 32); CPCOMMIT(); }
        const uint32_t abase = sA + (kt & 1) * (128 * 80) + (wm * 64 + rofA) * 80 + cofA * 2;
        const uint32_t bbase = sB + (kt & 1) * (128 * 80) + (wn * 32 + rofB) * 80 + cofB * 2;
        #pragma unroll
        for (int kc = 0; kc < 32; kc += 16) {
            uint32_t a[4][4], b[2][4];
            #pragma unroll
            for (int mt = 0; mt < 4; mt++)
                ldsm4(a[mt], abase + mt * (16 * 80) + kc * 2);
            #pragma unroll
            for (int pr = 0; pr < 2; pr++)
                ldsm4(b[pr], bbase + pr * (16 * 80) + kc * 2);
            #pragma unroll
            for (int mt = 0; mt < 4; mt++)
                #pragma unroll
                for (int pr = 0; pr < 2; pr++) {
                    mma16(acc[mt][2*pr    ], a[mt], &b[pr][0]);
                    mma16(acc[mt][2*pr + 1], a[mt], &b[pr][2]);
                }
        }
    }
}

// ---------------------------------------------------------------------------
// Q,K projection -> head-split bf16 [bh][s][64]. grid (32,8,2)
// ---------------------------------------------------------------------------
__global__ __launch_bounds__(256, 2) void qk_gemm(const float* __restrict__ bq,
                                                  const float* __restrict__ bk)
{
    __shared__ bf16 As[2*128*40], Bs[2*128*40];
    const int which = blockIdx.z;
    const bf16* W     = which ? g_wkb : g_wqb;
    const float* bias = which ? bk : bq;
    bf16* out         = which ? g_k : g_q;
    const float scale = which ? 1.0f : 0.125f;

    const int m0 = blockIdx.x * 128;
    const int n0 = blockIdx.y * 128;

    float acc[4][4][4] = {};
    gemm_core(g_xb + (size_t)m0 * DD, W + (size_t)n0 * DD, As, Bs, acc);

    const int tid = threadIdx.x;
    const int warp = tid >> 5, lane = tid & 31;
    const int gID = lane >> 2, tig = lane & 3;
    const int wm = warp >> 2, wn = warp & 3;

    #pragma unroll
    for (int mt = 0; mt < 4; mt++) {
        #pragma unroll
        for (int nt = 0; nt < 4; nt++) {
            int n = n0 + wn * 32 + nt * 8 + 2 * tig;
            int head = n >> 6, d = n & 63;
            float b0 = bias[n], b1 = bias[n + 1];
            #pragma unroll
            for (int half = 0; half < 2; half++) {
                int m = m0 + wm * 64 + mt * 16 + gID + half * 8;
                int bb = m >> 11, s = m & (SS - 1);
                uint32_t p = packbf((acc[mt][nt][half*2+0] + b0) * scale,
                                    (acc[mt][nt][half*2+1] + b1) * scale);
                *(uint32_t*)&out[((size_t)(bb * HH + head) * SS + s) * HD + d] = p;
            }
        }
    }
}

// ---------------------------------------------------------------------------
// V projection transposed: C[d][s]. grid (8, 16, B) -> g_vt bf16.
// ---------------------------------------------------------------------------
__global__ __launch_bounds__(256, 2) void v_gemm(const float* __restrict__ bv)
{
    __shared__ bf16 As[2*128*40], Bs[2*128*40];
    const int m0 = blockIdx.x * 128;          // d
    const int n0 = blockIdx.y * 128;          // s
    const int bb = blockIdx.z;

    float acc[4][4][4] = {};
    gemm_core(g_wvb + (size_t)m0 * DD,
              g_xb + ((size_t)bb * SS + n0) * DD, As, Bs, acc);

    const int tid = threadIdx.x;
    const int warp = tid >> 5, lane = tid & 31;
    const int gID = lane >> 2, tig = lane & 3;
    const int wm = warp >> 2, wn = warp & 3;

    #pragma unroll
    for (int mt = 0; mt < 4; mt++) {
        #pragma unroll
        for (int nt = 0; nt < 4; nt++) {
            int s = n0 + wn * 32 + nt * 8 + 2 * tig;
            #pragma unroll
            for (int half = 0; half < 2; half++) {
                int d = m0 + wm * 64 + mt * 16 + gID + half * 8;
                int head = d >> 6;
                float bia = bv[d];
                uint32_t p = packbf(acc[mt][nt][half*2+0] + bia,
                                    acc[mt][nt][half*2+1] + bia);
                *(uint32_t*)&g_vt[((size_t)(bb * HH + head) * HD + (d & 63)) * SS + s] = p;
            }
        }
    }
}

// ---------------------------------------------------------------------------
// Flash attention: q-tile 128, kv-tile 64, cp.async double-buffered K/V,
// single barrier per tile, 2 CTAs/SM. 8 warps, warp owns 16 q-rows.
// smem: Q 128x72 + 2x(K 64x72) + 2x(V 64x72) = 55296 B.
// ---------------------------------------------------------------------------
#define FL_SMEM ((128*72 + 2*64*72 + 2*64*72) * 2)

__global__ __launch_bounds__(256, 2) void flash_attn(const float* __restrict__ extra,
                                                     const float* __restrict__ mask)
{
    extern __shared__ bf16 smb[];
    bf16* Qs = smb;                      // [128][72]
    bf16* Ks = Qs + 128*72;              // 2 x [64][72]  (kv x d)
    bf16* Vt = Ks + 2*64*72;             // 2 x [64][72]  (d x kv)

    const int q0 = blockIdx.x * 128;
    const int bh = blockIdx.y;
    const int b  = bh >> 4;
    const int h  = bh & 15;
    const int tid = threadIdx.x;
    const int warp = tid >> 5, lane = tid & 31;
    const int gID = lane >> 2, tig = lane & 3;
    const int mrow = warp * 16;
    const int mat = lane >> 3, li = lane & 7;
    const int rofA = ((mat & 1) << 3) + li;
    const int cofA = (mat >> 1) << 3;
    const int rofB = ((mat >> 1) << 3) + li;
    const int cofB = (mat & 1) << 3;
    const unsigned FULL = 0xffffffffu;

    const bf16* qp  = g_q  + (size_t)bh * SS * HD;
    const bf16* kp  = g_k  + (size_t)bh * SS * HD;
    const bf16* vtp = g_vt + (size_t)bh * HD * SS;

    const uint32_t sQ = (uint32_t)__cvta_generic_to_shared(Qs);
    const uint32_t sK = (uint32_t)__cvta_generic_to_shared(Ks);
    const uint32_t sV = (uint32_t)__cvta_generic_to_shared(Vt);

    auto issueKV = [&](int buf, int k0) {
        #pragma unroll
        for (int r = 0; r < 2; r++) {
            int i = tid + r * 256;
            int row = i >> 3, seg = (i & 7) * 8;
            CP16(sK + (uint32_t)buf * (64*72*2) + (row*72 + seg)*2,
                 kp + (size_t)(k0 + row) * HD + seg);
            CP16(sV + (uint32_t)buf * (64*72*2) + (row*72 + seg)*2,
                 vtp + (size_t)row * SS + k0 + seg);
        }
    };

    issueKV(0, 0);
    CPCOMMIT();

    // Q tile 128x64 (plain loads overlap first cp.async)
    #pragma unroll
    for (int r = 0; r < 4; r++) {
        int c = tid + r * 256;
        int row = c >> 3, seg = (c & 7) * 8;
        *(uint4*)&Qs[row*72 + seg] = *(const uint4*)&qp[(size_t)(q0 + row) * HD + seg];
    }
    __syncthreads();

    // Hoist Q fragments into registers (4 kc-chunks x 4 regs)
    uint32_t qf[4][4];
    {
        uint32_t qbase = sQ + (mrow + rofA) * 144 + cofA * 2;
        #pragma unroll
        for (int c4 = 0; c4 < 4; c4++)
            ldsm4(qf[c4], qbase + c4 * 32);
    }

    float m_run[2] = {-INFINITY, -INFINITY};
    float l_run[2] = {0.f, 0.f};
    float o[8][4] = {};
    const int q_r0 = q0 + mrow + gID;

    for (int kt = 0; kt < SS / 64; kt++) {
        const int k0 = kt * 64;
        CPWAIT(0);
        __syncthreads();
        if (kt + 1 < SS / 64) { issueKV((kt + 1) & 1, k0 + 64); CPCOMMIT(); }

        const uint32_t kb = sK + (kt & 1) * (64*72*2) + rofB * 144 + cofB * 2;
        const uint32_t vb = sV + (kt & 1) * (64*72*2) + rofB * 144 + cofB * 2;

        // S = Q K^T  (warp 16 x 64, contraction d=64)
        float s[8][4] = {};
        #pragma unroll
        for (int c4 = 0; c4 < 4; c4++) {
            #pragma unroll
            for (int pr = 0; pr < 4; pr++) {
                uint32_t kf[4];
                ldsm4(kf, kb + pr * (16 * 144) + c4 * 32);
                mma16(s[2*pr    ], qf[c4], &kf[0]);
                mma16(s[2*pr + 1], qf[c4], &kf[2]);
            }
        }

        // add extra + mask; online softmax (rows gID, gID+8)
        const float* ep0 = extra + ((size_t)bh * SS + q_r0) * SS + k0;
        const float* ep1 = ep0 + (size_t)8 * SS;
        const float* mp0 = mask + ((size_t)b * SS + q_r0) * SS + k0;
        const float* mp1 = mp0 + (size_t)8 * SS;

        float mx0 = -INFINITY, mx1 = -INFINITY;
        #pragma unroll
        for (int nt = 0; nt < 8; nt++) {
            int c = nt * 8 + 2 * tig;
            float2 e0 = *(const float2*)&ep0[c];
            float2 e1 = *(const float2*)&ep1[c];
            float2 m0v = *(const float2*)&mp0[c];
            float2 m1v = *(const float2*)&mp1[c];
            s[nt][0] += e0.x + m0v.x;  s[nt][1] += e0.y + m0v.y;
            s[nt][2] += e1.x + m1v.x;  s[nt][3] += e1.y + m1v.y;
            mx0 = fmaxf(mx0, fmaxf(s[nt][0], s[nt][1]));
            mx1 = fmaxf(mx1, fmaxf(s[nt][2], s[nt][3]));
        }
        mx0 = fmaxf(mx0, __shfl_xor_sync(FULL, mx0, 1));
        mx0 = fmaxf(mx0, __shfl_xor_sync(FULL, mx0, 2));
        mx1 = fmaxf(mx1, __shfl_xor_sync(FULL, mx1, 1));
        mx1 = fmaxf(mx1, __shfl_xor_sync(FULL, mx1, 2));

        float mn0 = fmaxf(m_run[0], mx0);
        float mn1 = fmaxf(m_run[1], mx1);
        float corr0 = fexp(m_run[0] - mn0);
        float corr1 = fexp(m_run[1] - mn1);
        float ls0 = 0.f, ls1 = 0.f;
        #pragma unroll
        for (int nt = 0; nt < 8; nt++) {
            s[nt][0] = fexp(s[nt][0] - mn0);
            s[nt][1] = fexp(s[nt][1] - mn0);
            s[nt][2] = fexp(s[nt][2] - mn1);
            s[nt][3] = fexp(s[nt][3] - mn1);
            ls0 += s[nt][0] + s[nt][1];
            ls1 += s[nt][2] + s[nt][3];
        }
        ls0 += __shfl_xor_sync(FULL, ls0, 1);
        ls0 += __shfl_xor_sync(FULL, ls0, 2);
        ls1 += __shfl_xor_sync(FULL, ls1, 1);
        ls1 += __shfl_xor_sync(FULL, ls1, 2);
        l_run[0] = l_run[0] * corr0 + ls0;
        l_run[1] = l_run[1] * corr1 + ls1;
        m_run[0] = mn0;  m_run[1] = mn1;

        #pragma unroll
        for (int nt = 0; nt < 8; nt++) {
            o[nt][0] *= corr0;  o[nt][1] *= corr0;
            o[nt][2] *= corr1;  o[nt][3] *= corr1;
        }

        // O += P @ V   (contraction kv=64, P packed from score fragments)
        #pragma unroll
        for (int t = 0; t < 4; t++) {
            uint32_t a[4];
            a[0] = packbf(s[2*t    ][0], s[2*t    ][1]);
            a[1] = packbf(s[2*t    ][2], s[2*t    ][3]);
            a[2] = packbf(s[2*t + 1][0], s[2*t + 1][1]);
            a[3] = packbf(s[2*t + 1][2], s[2*t + 1][3]);
            #pragma unroll
            for (int pr = 0; pr < 4; pr++) {
                uint32_t vf[4];
                ldsm4(vf, vb + pr * (16 * 144) + t * 32);
                mma16(o[2*pr    ], a, &vf[0]);
                mma16(o[2*pr + 1], a, &vf[2]);
            }
        }
    }

    // write ctx bf16 [m][D]
    float inv0 = 1.0f / l_run[0];
    float inv1 = 1.0f / l_run[1];
    #pragma unroll
    for (int nt = 0; nt < 8; nt++) {
        int c = nt * 8 + 2 * tig;
        size_t base0 = ((size_t)(b * SS + q_r0    )) * DD + h * 64 + c;
        size_t base1 = ((size_t)(b * SS + q_r0 + 8)) * DD + h * 64 + c;
        *(uint32_t*)&g_ctx[base0] = packbf(o[nt][0] * inv0, o[nt][1] * inv0);
        *(uint32_t*)&g_ctx[base1] = packbf(o[nt][2] * inv1, o[nt][3] * inv1);
    }
}

// ---------------------------------------------------------------------------
// Output projection. grid (32, 8). fp32 out.
// ---------------------------------------------------------------------------
__global__ __launch_bounds__(256, 2) void out_proj(const float* __restrict__ bo)
{
    __shared__ bf16 As[2*128*40], Bs[2*128*40];
    const int m0 = blockIdx.x * 128;
    const int n0 = blockIdx.y * 128;

    float acc[4][4][4] = {};
    gemm_core(g_ctx + (size_t)m0 * DD, g_wob + (size_t)n0 * DD, As, Bs, acc);

    const int tid = threadIdx.x;
    const int warp = tid >> 5, lane = tid & 31;
    const int gID = lane >> 2, tig = lane & 3;
    const int wm = warp >> 2, wn = warp & 3;

    #pragma unroll
    for (int mt = 0; mt < 4; mt++) {
        #pragma unroll
        for (int nt = 0; nt < 4; nt++) {
            int n = n0 + wn * 32 + nt * 8 + 2 * tig;
            float b0 = bo[n], b1 = bo[n + 1];
            #pragma unroll
            for (int half = 0; half < 2; half++) {
                int m = m0 + wm * 64 + mt * 16 + gID + half * 8;
                float2 v;
                v.x = acc[mt][nt][half*2+0] + b0;
                v.y = acc[mt][nt][half*2+1] + b1;
                *(float2*)&g_attnout[(size_t)m * DD + n] = v;
            }
        }
    }
}

// ---------------------------------------------------------------------------
// residual + LayerNorm
// ---------------------------------------------------------------------------
__global__ void resid_ln(const float* __restrict__ hid,
                         const float* __restrict__ gamma,
                         const float* __restrict__ beta,
                         float* __restrict__ out)
{
    const int m = blockIdx.x;
    const int tid = threadIdx.x;
    const unsigned FULL = 0xffffffffu;

    float x[4];
    float sum = 0.f, sumsq = 0.f;
    #pragma unroll
    for (int r = 0; r < 4; r++) {
        int i = tid + r * 256;
        x[r] = hid[(size_t)m * DD + i] + g_attnout[(size_t)m * DD + i];
        sum += x[r];
        sumsq += x[r] * x[r];
    }
    #pragma unroll
    for (int off = 16; off > 0; off >>= 1) {
        sum   += __shfl_xor_sync(FULL, sum,   off);
        sumsq += __shfl_xor_sync(FULL, sumsq, off);
    }
    __shared__ float sh[2][8];
    int wid = tid >> 5, lane = tid & 31;
    if (lane == 0) { sh[0][wid] = sum; sh[1][wid] = sumsq; }
    __syncthreads();
    if (tid == 0) {
        float a = 0.f, c = 0.f;
        #pragma unroll
        for (int w = 0; w < 8; w++) { a += sh[0][w]; c += sh[1][w]; }
        sh[0][0] = a; sh[1][0] = c;
    }
    __syncthreads();
    float mu  = sh[0][0] * (1.0f / DD);
    float var = sh[1][0] * (1.0f / DD) - mu * mu;
    float inv = rsqrtf(var + LN_EPS);
    #pragma unroll
    for (int r = 0; r < 4; r++) {
        int i = tid + r * 256;
        out[(size_t)m * DD + i] = (x[r] - mu) * inv * gamma[i] + beta[i];
    }
}

// ---------------------------------------------------------------------------
extern "C" void kernel_launch(void* const* d_in, const int* in_sizes, int n_in,
                              void* d_out, int out_size)
{
    const float* hid   = (const float*)d_in[0];
    const float* mask  = (const float*)d_in[1];
    const float* extra = (const float*)d_in[2];
    const float* Wq = (const float*)d_in[3];  const float* bq = (const float*)d_in[4];
    const float* Wk = (const float*)d_in[5];  const float* bk = (const float*)d_in[6];
    const float* Wv = (const float*)d_in[7];  const float* bv = (const float*)d_in[8];
    const float* Wo = (const float*)d_in[9];  const float* bo = (const float*)d_in[10];
    const float* gamma = (const float*)d_in[11];
    const float* beta  = (const float*)d_in[12];
    float* out = (float*)d_out;

    bf16 *d_xb, *d_wqb, *d_wkb, *d_wvb, *d_wob;
    cudaGetSymbolAddress((void**)&d_xb,  g_xb);
    cudaGetSymbolAddress((void**)&d_wqb, g_wqb);
    cudaGetSymbolAddress((void**)&d_wkb, g_wkb);
    cudaGetSymbolAddress((void**)&d_wvb, g_wvb);
    cudaGetSymbolAddress((void**)&d_wob, g_wob);

    cudaFuncSetAttribute(flash_attn, cudaFuncAttributeMaxDynamicSharedMemorySize,
                         FL_SMEM);

    // launch order puts flash_attn at index 5 for ncu -s 5 -c 1
    conv_x <<<1024, 256>>>(hid, d_xb, MTOT*DD/4);                 // 0
    conv_w2<<<1024, 256>>>(Wq, Wk, d_wqb, d_wkb);                 // 1
    conv_w2<<<1024, 256>>>(Wv, Wo, d_wvb, d_wob);                 // 2
    qk_gemm<<<dim3(MTOT/128, DD/128, 2), 256>>>(bq, bk);          // 3
    v_gemm <<<dim3(DD/128, SS/128, BB), 256>>>(bv);               // 4
    flash_attn<<<dim3(SS/128, BHT), 256, FL_SMEM>>>(extra, mask); // 5
    out_proj<<<dim3(MTOT/128, DD/128), 256>>>(bo);                // 6
    resid_ln<<<MTOT, 256>>>(hid, gamma, beta, out);               // 7
}